// round 2
// baseline (speedup 1.0000x reference)
#include <cuda_runtime.h>
#include <cuda_bf16.h>
#include <math.h>

// Problem constants
#define BB 4
#define SS 1024
#define DD 512
#define HH 8
#define DKK 64
#define ROWS (BB*SS)          // 4096
#define NEGV (-1e9f)

// Scratch (device globals; no allocation allowed)
__device__ float g_Qp[ROWS*DD];
__device__ float g_Kp[ROWS*DD];
__device__ float g_Vp[ROWS*DD];
__device__ float g_ctx[ROWS*DD];

// ----------------------------------------------------------------------------
// Generic tiled GEMM: C[M,N] = A[M,K] @ B[K,N] (+ Res), BM=BN=128, BK=16,
// 256 threads, 8x8 microtile. Assumes M%128==0, N%128==0, K%16==0.
// ----------------------------------------------------------------------------
__global__ void gemm128(const float* __restrict__ A, const float* __restrict__ B,
                        const float* __restrict__ Res, float* __restrict__ C,
                        int K, int lda, int ldb, int ldc) {
    __shared__ float As[16][129];
    __shared__ float Bs[16][128];
    const int bm = blockIdx.y * 128;
    const int bn = blockIdx.x * 128;
    const int tid = threadIdx.x;
    const int ty = tid >> 4, tx = tid & 15;

    float acc[8][8];
#pragma unroll
    for (int i = 0; i < 8; i++)
#pragma unroll
        for (int j = 0; j < 8; j++) acc[i][j] = 0.f;

    for (int k0 = 0; k0 < K; k0 += 16) {
        // Load A tile: 128 rows x 16 k
#pragma unroll
        for (int l = 0; l < 8; l++) {
            int idx = tid + l * 256;          // 0..2047
            int r = idx >> 4, kk = idx & 15;
            As[kk][r] = A[(long)(bm + r) * lda + k0 + kk];
        }
        // Load B tile: 16 k x 128 cols
#pragma unroll
        for (int l = 0; l < 8; l++) {
            int idx = tid + l * 256;
            int kk = idx >> 7, c = idx & 127;
            Bs[kk][c] = B[(long)(k0 + kk) * ldb + bn + c];
        }
        __syncthreads();
#pragma unroll
        for (int kk = 0; kk < 16; kk++) {
            float a[8], b[8];
#pragma unroll
            for (int i = 0; i < 8; i++) a[i] = As[kk][ty + 16 * i];
#pragma unroll
            for (int j = 0; j < 8; j++) b[j] = Bs[kk][tx + 16 * j];
#pragma unroll
            for (int i = 0; i < 8; i++)
#pragma unroll
                for (int j = 0; j < 8; j++) acc[i][j] += a[i] * b[j];
        }
        __syncthreads();
    }

#pragma unroll
    for (int i = 0; i < 8; i++) {
        int r = bm + ty + 16 * i;
#pragma unroll
        for (int j = 0; j < 8; j++) {
            int c = bn + tx + 16 * j;
            float v = acc[i][j];
            if (Res) v += Res[(long)r * ldc + c];
            C[(long)r * ldc + c] = v;
        }
    }
}

// ----------------------------------------------------------------------------
// Scores + bias kernel. Block = (k-tile 64, q-tile 64, batch). 256 threads.
// Dynamic smem: Qt[64][65] f32, Kt[64][65] f32, bias[8][64][64] bf16.
// Writes raw (pre-softmax) scores into the attn output region.
// NOTE: attn_if is read as 4-byte words (nonzero test) — robust to the
// harness widening the bool to either int32 or float32.
// ----------------------------------------------------------------------------
__global__ void scores_kernel(const float* __restrict__ Qp, const float* __restrict__ Kp,
                              const int* __restrict__ attn_if,
                              const int* __restrict__ itype,
                              const float* __restrict__ im,
                              const float* __restrict__ type_emb,
                              const float* __restrict__ w_feat,
                              float* __restrict__ attn_out) {
    extern __shared__ char smraw[];
    float* Qt = (float*)smraw;                      // 64*65
    float* Kt = Qt + 64 * 65;                       // 64*65
    __nv_bfloat16* biasS = (__nv_bfloat16*)(Kt + 64 * 65);  // 8*64*64

    const int b = blockIdx.z;
    const int q0 = blockIdx.y * 64;
    const int k0 = blockIdx.x * 64;
    const int tid = threadIdx.x;

    __shared__ float wf[6][8];
    if (tid < 48) wf[tid / 8][tid % 8] = w_feat[tid];
    __syncthreads();

    // Step A: per-pair bias for all 8 heads (computed once).
#pragma unroll
    for (int l = 0; l < 16; l++) {
        int idx = tid + l * 256;                    // 0..4095
        int qi = idx >> 6, ki = idx & 63;
        long pair = ((long)(b * SS + q0 + qi)) * SS + (k0 + ki);
        if (attn_if[pair] != 0) {
#pragma unroll
            for (int h = 0; h < 8; h++)
                biasS[h * 4096 + qi * 64 + ki] = __float2bfloat16(NEGV);
        } else {
            int t = itype[pair];
            const float* e = type_emb + (long)t * 8;
            float f0 = im[pair * 6 + 0], f1 = im[pair * 6 + 1], f2 = im[pair * 6 + 2];
            float f3 = im[pair * 6 + 3], f4 = im[pair * 6 + 4], f5 = im[pair * 6 + 5];
#pragma unroll
            for (int h = 0; h < 8; h++) {
                float s = f0 * wf[0][h] + f1 * wf[1][h] + f2 * wf[2][h]
                        + f3 * wf[3][h] + f4 * wf[4][h] + f5 * wf[5][h];
                s = fmaxf(s, 0.f) + e[h];
                biasS[h * 4096 + qi * 64 + ki] = __float2bfloat16(s);
            }
        }
    }

    const int ty = tid >> 4, tx = tid & 15;
    for (int h = 0; h < 8; h++) {
        __syncthreads();
        // Load Q/K tiles for head h
#pragma unroll
        for (int l = 0; l < 16; l++) {
            int idx = tid + l * 256;
            int r = idx >> 6, d = idx & 63;
            Qt[r * 65 + d] = Qp[((long)(b * SS + q0 + r)) * DD + h * 64 + d];
            Kt[r * 65 + d] = Kp[((long)(b * SS + k0 + r)) * DD + h * 64 + d];
        }
        __syncthreads();

        float acc[4][4];
#pragma unroll
        for (int i = 0; i < 4; i++)
#pragma unroll
            for (int j = 0; j < 4; j++) acc[i][j] = 0.f;

#pragma unroll
        for (int d = 0; d < 64; d++) {
            float a[4], kv[4];
#pragma unroll
            for (int i = 0; i < 4; i++) a[i] = Qt[(ty + 16 * i) * 65 + d];
#pragma unroll
            for (int j = 0; j < 4; j++) kv[j] = Kt[(tx + 16 * j) * 65 + d];
#pragma unroll
            for (int i = 0; i < 4; i++)
#pragma unroll
                for (int j = 0; j < 4; j++) acc[i][j] += a[i] * kv[j];
        }

        float* outp = attn_out + (((long)(b * HH + h) * SS + q0)) * SS + k0;
#pragma unroll
        for (int i = 0; i < 4; i++) {
            int qi = ty + 16 * i;
#pragma unroll
            for (int j = 0; j < 4; j++) {
                int ki = tx + 16 * j;
                float bias = __bfloat162float(biasS[h * 4096 + qi * 64 + ki]);
                outp[(long)qi * SS + ki] = acc[i][j] * 0.125f + bias;
            }
        }
    }
}

// ----------------------------------------------------------------------------
// Row softmax in place over attn [B*H*S, S]. 256 threads, 4 elems/thread.
// ----------------------------------------------------------------------------
__global__ void softmax_kernel(float* __restrict__ attn) {
    const long row = blockIdx.x;
    float* p = attn + row * SS;
    const int tid = threadIdx.x;
    float v[4];
    float mx = -INFINITY;
#pragma unroll
    for (int i = 0; i < 4; i++) { v[i] = p[tid + 256 * i]; mx = fmaxf(mx, v[i]); }
#pragma unroll
    for (int o = 16; o; o >>= 1) mx = fmaxf(mx, __shfl_xor_sync(0xffffffffu, mx, o));
    __shared__ float rmx[8], rsm[8];
    if ((tid & 31) == 0) rmx[tid >> 5] = mx;
    __syncthreads();
    float bm = rmx[0];
#pragma unroll
    for (int w = 1; w < 8; w++) bm = fmaxf(bm, rmx[w]);
    float s = 0.f;
#pragma unroll
    for (int i = 0; i < 4; i++) { v[i] = __expf(v[i] - bm); s += v[i]; }
#pragma unroll
    for (int o = 16; o; o >>= 1) s += __shfl_xor_sync(0xffffffffu, s, o);
    if ((tid & 31) == 0) rsm[tid >> 5] = s;
    __syncthreads();
    float tot = 0.f;
#pragma unroll
    for (int w = 0; w < 8; w++) tot += rsm[w];
    float inv = 1.f / tot;
#pragma unroll
    for (int i = 0; i < 4; i++) p[tid + 256 * i] = v[i] * inv;
}

// ----------------------------------------------------------------------------
// ctx[b,q,h*64+j] = sum_k attn[b,h,q,k] * Vp[b,k,h*64+j]. 64x64 tile, 4x4 micro.
// grid: (1, S/64, B*H)
// ----------------------------------------------------------------------------
__global__ void av_kernel(const float* __restrict__ attn, const float* __restrict__ Vp,
                          float* __restrict__ ctx) {
    __shared__ float As[32][65];
    __shared__ float Bs[32][64];
    const int z = blockIdx.z;              // b*H + h
    const int b = z >> 3, h = z & 7;
    const int q0 = blockIdx.y * 64;
    const float* A = attn + (long)z * SS * SS;
    const float* Bv = Vp + (long)b * SS * DD + h * 64;
    const int tid = threadIdx.x;
    const int ty = tid >> 4, tx = tid & 15;

    float acc[4][4];
#pragma unroll
    for (int i = 0; i < 4; i++)
#pragma unroll
        for (int j = 0; j < 4; j++) acc[i][j] = 0.f;

    for (int k0 = 0; k0 < SS; k0 += 32) {
#pragma unroll
        for (int l = 0; l < 8; l++) {
            int idx = tid + l * 256;       // 0..2047
            int r = idx >> 5, kk = idx & 31;
            As[kk][r] = A[(long)(q0 + r) * SS + k0 + kk];
        }
#pragma unroll
        for (int l = 0; l < 8; l++) {
            int idx = tid + l * 256;
            int kk = idx >> 6, c = idx & 63;
            Bs[kk][c] = Bv[(long)(k0 + kk) * DD + c];
        }
        __syncthreads();
#pragma unroll
        for (int kk = 0; kk < 32; kk++) {
            float a[4], bvv[4];
#pragma unroll
            for (int i = 0; i < 4; i++) a[i] = As[kk][ty + 16 * i];
#pragma unroll
            for (int j = 0; j < 4; j++) bvv[j] = Bs[kk][tx + 16 * j];
#pragma unroll
            for (int i = 0; i < 4; i++)
#pragma unroll
                for (int j = 0; j < 4; j++) acc[i][j] += a[i] * bvv[j];
        }
        __syncthreads();
    }

    float* C = ctx + (long)b * SS * DD + h * 64;
#pragma unroll
    for (int i = 0; i < 4; i++)
#pragma unroll
        for (int j = 0; j < 4; j++)
            C[(long)(q0 + ty + 16 * i) * DD + tx + 16 * j] = acc[i][j];
}

// ----------------------------------------------------------------------------
// In-place LayerNorm over last dim (512). grid = ROWS, 256 threads.
// ----------------------------------------------------------------------------
__global__ void ln_kernel(float* __restrict__ out, const float* __restrict__ g,
                          const float* __restrict__ bta) {
    const long row = blockIdx.x;
    float* p = out + row * DD;
    const int tid = threadIdx.x;
    float x0 = p[tid], x1 = p[tid + 256];
    float s = x0 + x1, ss = x0 * x0 + x1 * x1;
#pragma unroll
    for (int o = 16; o; o >>= 1) {
        s += __shfl_xor_sync(0xffffffffu, s, o);
        ss += __shfl_xor_sync(0xffffffffu, ss, o);
    }
    __shared__ float rs[8], rss[8];
    if ((tid & 31) == 0) { rs[tid >> 5] = s; rss[tid >> 5] = ss; }
    __syncthreads();
    float S = 0.f, SSq = 0.f;
#pragma unroll
    for (int w = 0; w < 8; w++) { S += rs[w]; SSq += rss[w]; }
    float mu = S * (1.f / 512.f);
    float var = SSq * (1.f / 512.f) - mu * mu;
    float inv = rsqrtf(var + 1e-5f);
    p[tid] = (x0 - mu) * inv * g[tid] + bta[tid];
    p[tid + 256] = (x1 - mu) * inv * g[tid + 256] + bta[tid + 256];
}

// ----------------------------------------------------------------------------
extern "C" void kernel_launch(void* const* d_in, const int* in_sizes, int n_in,
                              void* d_out, int out_size) {
    const float* input_Q = (const float*)d_in[0];
    const float* input_K = (const float*)d_in[1];
    const float* input_V = (const float*)d_in[2];
    // d_in[3] attn_mask: unused by reference
    const int* attn_if = (const int*)d_in[4];   // bool widened to 4-byte (int32 or f32; nonzero test works for both)
    const int* itype = (const int*)d_in[5];
    const float* im = (const float*)d_in[6];
    // d_in[7] res_mass_centor, d_in[8] distance_matrix: unused
    const float* w_q = (const float*)d_in[9];
    const float* w_k = (const float*)d_in[10];
    const float* w_v = (const float*)d_in[11];
    const float* w_fc = (const float*)d_in[12];
    const float* ln_g = (const float*)d_in[13];
    const float* ln_b = (const float*)d_in[14];
    const float* type_emb = (const float*)d_in[15];
    const float* w_feat = (const float*)d_in[16];

    float* out = (float*)d_out;
    float* attn = out + (size_t)ROWS * DD;

    float *Qp, *Kp, *Vp, *ctx;
    cudaGetSymbolAddress((void**)&Qp, g_Qp);
    cudaGetSymbolAddress((void**)&Kp, g_Kp);
    cudaGetSymbolAddress((void**)&Vp, g_Vp);
    cudaGetSymbolAddress((void**)&ctx, g_ctx);

    // Projections: [4096,512] @ [512,512]
    dim3 gproj(DD / 128, ROWS / 128);
    gemm128<<<gproj, 256>>>(input_Q, w_q, nullptr, Qp, DD, DD, DD, DD);
    gemm128<<<gproj, 256>>>(input_K, w_k, nullptr, Kp, DD, DD, DD, DD);
    gemm128<<<gproj, 256>>>(input_V, w_v, nullptr, Vp, DD, DD, DD, DD);

    // Scores + bias -> attn region (raw)
    size_t smem = (size_t)(64 * 65 * 2) * sizeof(float) + (size_t)8 * 64 * 64 * sizeof(__nv_bfloat16);
    cudaFuncSetAttribute(scores_kernel, cudaFuncAttributeMaxDynamicSharedMemorySize, (int)smem);
    dim3 gsc(SS / 64, SS / 64, BB);
    scores_kernel<<<gsc, 256, smem>>>(Qp, Kp, attn_if, itype, im, type_emb, w_feat, attn);

    // Softmax in place
    softmax_kernel<<<BB * HH * SS, 256>>>(attn);

    // attn @ V -> ctx
    dim3 gav(1, SS / 64, BB * HH);
    av_kernel<<<gav, 256>>>(attn, Vp, ctx);

    // FC + residual -> out region
    gemm128<<<gproj, 256>>>(ctx, w_fc, input_Q, out, DD, DD, DD, DD);

    // LayerNorm in place
    ln_kernel<<<ROWS, 256>>>(out, ln_g, ln_b);
}

// round 3
// speedup vs baseline: 1.1431x; 1.1431x over previous
#include <cuda_runtime.h>
#include <cuda_bf16.h>
#include <math.h>

// Problem constants
#define BB 4
#define SS 1024
#define DD 512
#define HH 8
#define ROWS (BB*SS)          // 4096
#define NEGV (-1e9f)

// Scratch (device globals; no allocation allowed)
__device__ float g_Qp[ROWS*DD];
__device__ float g_Kp[ROWS*DD];
__device__ float g_Vp[ROWS*DD];
__device__ float g_ctx[ROWS*DD];

// ----------------------------------------------------------------------------
// GEMM body: C[M,N] = A[M,K] @ B[K,N] (+ Res). BM=128, BN=128, BK=16,
// 256 threads, 8x8 microtile on CONTIGUOUS rows/cols -> LDS.128 operand fetch.
// ----------------------------------------------------------------------------
__device__ __forceinline__ void gemm_body(const float* __restrict__ A,
                                          const float* __restrict__ B,
                                          const float* __restrict__ Res,
                                          float* __restrict__ C,
                                          int K, int lda, int ldb, int ldc,
                                          int bm, int bn) {
    __shared__ float As[16 * 132];   // k-major: As[kk][r], stride 132 (16B aligned)
    __shared__ float Bs[16 * 128];   // Bs[kk][c]
    const int tid = threadIdx.x;
    const int ty = tid >> 4, tx = tid & 15;   // 16x16 threads, 8x8 micro

    float acc[8][8];
#pragma unroll
    for (int i = 0; i < 8; i++)
#pragma unroll
        for (int j = 0; j < 8; j++) acc[i][j] = 0.f;

    const int fA = tid & 3;          // float4 index within 16 k
    const int rA = tid >> 2;         // 0..63
    const int cB = tid & 31;         // float4 index within 128 cols
    const int kB = tid >> 5;         // 0..7

    for (int k0 = 0; k0 < K; k0 += 16) {
        // A tile: 128 rows x 16 k (2 float4 per thread)
#pragma unroll
        for (int l = 0; l < 2; l++) {
            int r = rA + l * 64;
            float4 v = *(const float4*)&A[(long)(bm + r) * lda + k0 + 4 * fA];
            As[(4 * fA + 0) * 132 + r] = v.x;
            As[(4 * fA + 1) * 132 + r] = v.y;
            As[(4 * fA + 2) * 132 + r] = v.z;
            As[(4 * fA + 3) * 132 + r] = v.w;
        }
        // B tile: 16 k x 128 cols (2 float4 per thread, vector stores)
#pragma unroll
        for (int l = 0; l < 2; l++) {
            int kk = kB + l * 8;
            float4 v = *(const float4*)&B[(long)(k0 + kk) * ldb + bn + 4 * cB];
            *(float4*)&Bs[kk * 128 + 4 * cB] = v;
        }
        __syncthreads();
#pragma unroll
        for (int kk = 0; kk < 16; kk++) {
            float4 a0 = *(const float4*)&As[kk * 132 + 8 * ty];
            float4 a1 = *(const float4*)&As[kk * 132 + 8 * ty + 4];
            float4 b0 = *(const float4*)&Bs[kk * 128 + 8 * tx];
            float4 b1 = *(const float4*)&Bs[kk * 128 + 8 * tx + 4];
            float a[8] = {a0.x, a0.y, a0.z, a0.w, a1.x, a1.y, a1.z, a1.w};
            float b[8] = {b0.x, b0.y, b0.z, b0.w, b1.x, b1.y, b1.z, b1.w};
#pragma unroll
            for (int i = 0; i < 8; i++)
#pragma unroll
                for (int j = 0; j < 8; j++) acc[i][j] += a[i] * b[j];
        }
        __syncthreads();
    }

#pragma unroll
    for (int i = 0; i < 8; i++) {
        long r = bm + 8 * ty + i;
#pragma unroll
        for (int jj = 0; jj < 2; jj++) {
            long c = bn + 8 * tx + 4 * jj;
            float4 v = make_float4(acc[i][4*jj], acc[i][4*jj+1], acc[i][4*jj+2], acc[i][4*jj+3]);
            if (Res) {
                float4 rr = *(const float4*)&Res[r * ldc + c];
                v.x += rr.x; v.y += rr.y; v.z += rr.z; v.w += rr.w;
            }
            *(float4*)&C[r * ldc + c] = v;
        }
    }
}

// Fused Q/K/V projections: grid.z selects which projection.
__global__ __launch_bounds__(256) void proj3_kernel(
        const float* __restrict__ Aq, const float* __restrict__ Ak, const float* __restrict__ Av,
        const float* __restrict__ Wq, const float* __restrict__ Wk, const float* __restrict__ Wv,
        float* __restrict__ Cq, float* __restrict__ Ck, float* __restrict__ Cv) {
    const int z = blockIdx.z;
    const float* A = (z == 0) ? Aq : (z == 1) ? Ak : Av;
    const float* B = (z == 0) ? Wq : (z == 1) ? Wk : Wv;
    float*       C = (z == 0) ? Cq : (z == 1) ? Ck : Cv;
    gemm_body(A, B, nullptr, C, DD, DD, DD, DD, blockIdx.y * 128, blockIdx.x * 128);
}

__global__ __launch_bounds__(256) void fc_kernel(const float* __restrict__ A,
                                                 const float* __restrict__ B,
                                                 const float* __restrict__ Res,
                                                 float* __restrict__ C) {
    gemm_body(A, B, Res, C, DD, DD, DD, DD, blockIdx.y * 128, blockIdx.x * 128);
}

// ----------------------------------------------------------------------------
// Scores + bias. Block = (k-tile 64, q-tile 64, batch). 256 threads.
// Qt/Kt stored TRANSPOSED [d][r] (stride 68) -> LDS.128 operand fetch.
// bias[8][64][64] bf16 computed once for all heads.
// ----------------------------------------------------------------------------
__global__ __launch_bounds__(256) void scores_kernel(
        const float* __restrict__ Qp, const float* __restrict__ Kp,
        const int* __restrict__ attn_if, const int* __restrict__ itype,
        const float* __restrict__ im, const float* __restrict__ type_emb,
        const float* __restrict__ w_feat, float* __restrict__ attn_out) {
    extern __shared__ char smraw[];
    float* Qt = (float*)smraw;                       // 64 d x 68
    float* Kt = Qt + 64 * 68;                        // 64 d x 68
    __nv_bfloat16* biasS = (__nv_bfloat16*)(Kt + 64 * 68);  // 8*64*64

    const int b = blockIdx.z;
    const int q0 = blockIdx.y * 64;
    const int k0 = blockIdx.x * 64;
    const int tid = threadIdx.x;

    __shared__ float wf[6][8];
    if (tid < 48) wf[tid / 8][tid % 8] = w_feat[tid];
    __syncthreads();

    // Per-pair bias for all 8 heads (computed once).
#pragma unroll
    for (int l = 0; l < 16; l++) {
        int idx = tid + l * 256;                     // 0..4095
        int qi = idx >> 6, ki = idx & 63;
        long pair = ((long)(b * SS + q0 + qi)) * SS + (k0 + ki);
        if (attn_if[pair] != 0) {
#pragma unroll
            for (int h = 0; h < 8; h++)
                biasS[h * 4096 + qi * 64 + ki] = __float2bfloat16(NEGV);
        } else {
            int t = itype[pair];
            const float* e = type_emb + (long)t * 8;
            const float2* imp = (const float2*)(im + pair * 6);
            float2 p0 = imp[0], p1 = imp[1], p2 = imp[2];
#pragma unroll
            for (int h = 0; h < 8; h++) {
                float s = p0.x * wf[0][h] + p0.y * wf[1][h] + p1.x * wf[2][h]
                        + p1.y * wf[3][h] + p2.x * wf[4][h] + p2.y * wf[5][h];
                s = fmaxf(s, 0.f) + e[h];
                biasS[h * 4096 + qi * 64 + ki] = __float2bfloat16(s);
            }
        }
    }

    const int ty = tid >> 4, tx = tid & 15;          // rows 4ty.., cols 4tx..
    const int fL = tid & 15;                         // float4 idx within 64 d
    const int rL = tid >> 4;                         // 0..15

    for (int h = 0; h < 8; h++) {
        __syncthreads();
        // Load Q/K tiles (transposed into smem)
#pragma unroll
        for (int l = 0; l < 4; l++) {
            int r = rL + l * 16;
            float4 q = *(const float4*)&Qp[((long)(b * SS + q0 + r)) * DD + h * 64 + 4 * fL];
            float4 k = *(const float4*)&Kp[((long)(b * SS + k0 + r)) * DD + h * 64 + 4 * fL];
            Qt[(4 * fL + 0) * 68 + r] = q.x;  Kt[(4 * fL + 0) * 68 + r] = k.x;
            Qt[(4 * fL + 1) * 68 + r] = q.y;  Kt[(4 * fL + 1) * 68 + r] = k.y;
            Qt[(4 * fL + 2) * 68 + r] = q.z;  Kt[(4 * fL + 2) * 68 + r] = k.z;
            Qt[(4 * fL + 3) * 68 + r] = q.w;  Kt[(4 * fL + 3) * 68 + r] = k.w;
        }
        __syncthreads();

        float acc[4][4];
#pragma unroll
        for (int i = 0; i < 4; i++)
#pragma unroll
            for (int j = 0; j < 4; j++) acc[i][j] = 0.f;

#pragma unroll
        for (int d = 0; d < 64; d++) {
            float4 a4 = *(const float4*)&Qt[d * 68 + 4 * ty];
            float4 b4 = *(const float4*)&Kt[d * 68 + 4 * tx];
            float a[4] = {a4.x, a4.y, a4.z, a4.w};
            float bb[4] = {b4.x, b4.y, b4.z, b4.w};
#pragma unroll
            for (int i = 0; i < 4; i++)
#pragma unroll
                for (int j = 0; j < 4; j++) acc[i][j] += a[i] * bb[j];
        }

        float* outp = attn_out + (((long)(b * HH + h) * SS + q0)) * SS + k0;
#pragma unroll
        for (int i = 0; i < 4; i++) {
            int qi = 4 * ty + i;
            const __nv_bfloat16* bp = &biasS[h * 4096 + qi * 64 + 4 * tx];
            float4 v;
            v.x = acc[i][0] * 0.125f + __bfloat162float(bp[0]);
            v.y = acc[i][1] * 0.125f + __bfloat162float(bp[1]);
            v.z = acc[i][2] * 0.125f + __bfloat162float(bp[2]);
            v.w = acc[i][3] * 0.125f + __bfloat162float(bp[3]);
            *(float4*)&outp[(long)qi * SS + 4 * tx] = v;
        }
    }
}

// ----------------------------------------------------------------------------
// Row softmax in place over attn [B*H*S, S]. 256 threads, 4 elems/thread.
// ----------------------------------------------------------------------------
__global__ void softmax_kernel(float* __restrict__ attn) {
    const long row = blockIdx.x;
    float* p = attn + row * SS;
    const int tid = threadIdx.x;
    float v[4];
    float mx = -INFINITY;
#pragma unroll
    for (int i = 0; i < 4; i++) { v[i] = p[tid + 256 * i]; mx = fmaxf(mx, v[i]); }
#pragma unroll
    for (int o = 16; o; o >>= 1) mx = fmaxf(mx, __shfl_xor_sync(0xffffffffu, mx, o));
    __shared__ float rmx[8], rsm[8];
    if ((tid & 31) == 0) rmx[tid >> 5] = mx;
    __syncthreads();
    float bm = rmx[0];
#pragma unroll
    for (int w = 1; w < 8; w++) bm = fmaxf(bm, rmx[w]);
    float s = 0.f;
#pragma unroll
    for (int i = 0; i < 4; i++) { v[i] = __expf(v[i] - bm); s += v[i]; }
#pragma unroll
    for (int o = 16; o; o >>= 1) s += __shfl_xor_sync(0xffffffffu, s, o);
    if ((tid & 31) == 0) rsm[tid >> 5] = s;
    __syncthreads();
    float tot = 0.f;
#pragma unroll
    for (int w = 0; w < 8; w++) tot += rsm[w];
    float inv = 1.f / tot;
#pragma unroll
    for (int i = 0; i < 4; i++) p[tid + 256 * i] = v[i] * inv;
}

// ----------------------------------------------------------------------------
// ctx = attn @ V per (b,h). 128x64 tile, BK=32, 8x4 microtile, LDS.128 fetch.
// grid: (1, S/128, B*H)
// ----------------------------------------------------------------------------
__global__ __launch_bounds__(256) void av_kernel(const float* __restrict__ attn,
                                                 const float* __restrict__ Vp,
                                                 float* __restrict__ ctx) {
    __shared__ float As[32 * 132];   // k-major [kk][r], 128 rows
    __shared__ float Bs[32 * 64];    // [kk][c], 64 cols
    const int z = blockIdx.z;        // b*H + h
    const int b = z >> 3, h = z & 7;
    const int q0 = blockIdx.y * 128;
    const float* A = attn + (long)z * SS * SS;
    const float* Bv = Vp + (long)b * SS * DD + h * 64;
    const int tid = threadIdx.x;
    const int ty = tid >> 4, tx = tid & 15;   // rows 8ty.., cols 4tx..

    float acc[8][4];
#pragma unroll
    for (int i = 0; i < 8; i++)
#pragma unroll
        for (int j = 0; j < 4; j++) acc[i][j] = 0.f;

    const int fA = tid & 7;          // float4 idx within 32 k
    const int rA = tid >> 3;         // 0..31
    const int cB = tid & 15;         // float4 idx within 64 cols
    const int kB = tid >> 4;         // 0..15

    for (int k0 = 0; k0 < SS; k0 += 32) {
#pragma unroll
        for (int l = 0; l < 4; l++) {
            int r = rA + l * 32;
            float4 v = *(const float4*)&A[(long)(q0 + r) * SS + k0 + 4 * fA];
            As[(4 * fA + 0) * 132 + r] = v.x;
            As[(4 * fA + 1) * 132 + r] = v.y;
            As[(4 * fA + 2) * 132 + r] = v.z;
            As[(4 * fA + 3) * 132 + r] = v.w;
        }
#pragma unroll
        for (int l = 0; l < 2; l++) {
            int kk = kB + l * 16;
            float4 v = *(const float4*)&Bv[(long)(k0 + kk) * DD + 4 * cB];
            *(float4*)&Bs[kk * 64 + 4 * cB] = v;
        }
        __syncthreads();
#pragma unroll
        for (int kk = 0; kk < 32; kk++) {
            float4 a0 = *(const float4*)&As[kk * 132 + 8 * ty];
            float4 a1 = *(const float4*)&As[kk * 132 + 8 * ty + 4];
            float4 b4 = *(const float4*)&Bs[kk * 64 + 4 * tx];
            float a[8] = {a0.x, a0.y, a0.z, a0.w, a1.x, a1.y, a1.z, a1.w};
            float bb[4] = {b4.x, b4.y, b4.z, b4.w};
#pragma unroll
            for (int i = 0; i < 8; i++)
#pragma unroll
                for (int j = 0; j < 4; j++) acc[i][j] += a[i] * bb[j];
        }
        __syncthreads();
    }

    float* C = ctx + (long)b * SS * DD + h * 64;
#pragma unroll
    for (int i = 0; i < 8; i++) {
        float4 v = make_float4(acc[i][0], acc[i][1], acc[i][2], acc[i][3]);
        *(float4*)&C[(long)(q0 + 8 * ty + i) * DD + 4 * tx] = v;
    }
}

// ----------------------------------------------------------------------------
// In-place LayerNorm over last dim (512). grid = ROWS, 256 threads.
// ----------------------------------------------------------------------------
__global__ void ln_kernel(float* __restrict__ out, const float* __restrict__ g,
                          const float* __restrict__ bta) {
    const long row = blockIdx.x;
    float* p = out + row * DD;
    const int tid = threadIdx.x;
    float x0 = p[tid], x1 = p[tid + 256];
    float s = x0 + x1, ss = x0 * x0 + x1 * x1;
#pragma unroll
    for (int o = 16; o; o >>= 1) {
        s += __shfl_xor_sync(0xffffffffu, s, o);
        ss += __shfl_xor_sync(0xffffffffu, ss, o);
    }
    __shared__ float rs[8], rss[8];
    if ((tid & 31) == 0) { rs[tid >> 5] = s; rss[tid >> 5] = ss; }
    __syncthreads();
    float S = 0.f, SSq = 0.f;
#pragma unroll
    for (int w = 0; w < 8; w++) { S += rs[w]; SSq += rss[w]; }
    float mu = S * (1.f / 512.f);
    float var = SSq * (1.f / 512.f) - mu * mu;
    float inv = rsqrtf(var + 1e-5f);
    p[tid] = (x0 - mu) * inv * g[tid] + bta[tid];
    p[tid + 256] = (x1 - mu) * inv * g[tid + 256] + bta[tid + 256];
}

// ----------------------------------------------------------------------------
extern "C" void kernel_launch(void* const* d_in, const int* in_sizes, int n_in,
                              void* d_out, int out_size) {
    const float* input_Q = (const float*)d_in[0];
    const float* input_K = (const float*)d_in[1];
    const float* input_V = (const float*)d_in[2];
    const int* attn_if = (const int*)d_in[4];   // bool widened to 4 bytes
    const int* itype = (const int*)d_in[5];
    const float* im = (const float*)d_in[6];
    const float* w_q = (const float*)d_in[9];
    const float* w_k = (const float*)d_in[10];
    const float* w_v = (const float*)d_in[11];
    const float* w_fc = (const float*)d_in[12];
    const float* ln_g = (const float*)d_in[13];
    const float* ln_b = (const float*)d_in[14];
    const float* type_emb = (const float*)d_in[15];
    const float* w_feat = (const float*)d_in[16];

    float* out = (float*)d_out;
    float* attn = out + (size_t)ROWS * DD;

    float *Qp, *Kp, *Vp, *ctx;
    cudaGetSymbolAddress((void**)&Qp, g_Qp);
    cudaGetSymbolAddress((void**)&Kp, g_Kp);
    cudaGetSymbolAddress((void**)&Vp, g_Vp);
    cudaGetSymbolAddress((void**)&ctx, g_ctx);

    // Fused projections: [4096,512] @ [512,512] x3
    dim3 gproj(DD / 128, ROWS / 128, 3);
    proj3_kernel<<<gproj, 256>>>(input_Q, input_K, input_V, w_q, w_k, w_v, Qp, Kp, Vp);

    // Scores + bias -> attn region (raw)
    size_t smem = (size_t)(2 * 64 * 68) * sizeof(float) + (size_t)8 * 64 * 64 * sizeof(__nv_bfloat16);
    cudaFuncSetAttribute(scores_kernel, cudaFuncAttributeMaxDynamicSharedMemorySize, (int)smem);
    dim3 gsc(SS / 64, SS / 64, BB);
    scores_kernel<<<gsc, 256, smem>>>(Qp, Kp, attn_if, itype, im, type_emb, w_feat, attn);

    // Softmax in place
    softmax_kernel<<<BB * HH * SS, 256>>>(attn);

    // attn @ V -> ctx
    dim3 gav(1, SS / 128, BB * HH);
    av_kernel<<<gav, 256>>>(attn, Vp, ctx);

    // FC + residual -> out region
    dim3 gfc(DD / 128, ROWS / 128);
    fc_kernel<<<gfc, 256>>>(ctx, w_fc, input_Q, out);

    // LayerNorm in place
    ln_kernel<<<ROWS, 256>>>(out, ln_g, ln_b);
}

// round 4
// speedup vs baseline: 1.4051x; 1.2292x over previous
#include <cuda_runtime.h>
#include <cuda_bf16.h>
#include <math.h>
#include <stdint.h>

// Problem constants
#define BB 4
#define SS 1024
#define DD 512
#define HH 8
#define ROWS (BB*SS)          // 4096
#define NEGV (-1e9f)

// Scratch (device globals; no allocation allowed)
__device__ float g_Qp[ROWS*DD];
__device__ float g_Kp[ROWS*DD];
__device__ __nv_bfloat16 g_Vpb[ROWS*DD];
__device__ __nv_bfloat16 g_ctxb[ROWS*DD];
__device__ __nv_bfloat16 g_attnb[BB*HH*SS*SS];
__device__ __nv_bfloat16 g_wfcb[DD*DD];

// ============================ MMA helpers ===================================
__device__ __forceinline__ uint32_t smem_u32(const void* p) {
    return (uint32_t)__cvta_generic_to_shared(p);
}
__device__ __forceinline__ void ldsm_x4(uint32_t& r0, uint32_t& r1, uint32_t& r2, uint32_t& r3, uint32_t addr) {
    asm volatile("ldmatrix.sync.aligned.m8n8.x4.shared.b16 {%0,%1,%2,%3}, [%4];\n"
        : "=r"(r0), "=r"(r1), "=r"(r2), "=r"(r3) : "r"(addr));
}
__device__ __forceinline__ void ldsm_x4_t(uint32_t& r0, uint32_t& r1, uint32_t& r2, uint32_t& r3, uint32_t addr) {
    asm volatile("ldmatrix.sync.aligned.m8n8.x4.trans.shared.b16 {%0,%1,%2,%3}, [%4];\n"
        : "=r"(r0), "=r"(r1), "=r"(r2), "=r"(r3) : "r"(addr));
}
__device__ __forceinline__ void mma_bf16(float& c0, float& c1, float& c2, float& c3,
        uint32_t a0, uint32_t a1, uint32_t a2, uint32_t a3, uint32_t b0, uint32_t b1) {
    asm volatile("mma.sync.aligned.m16n8k16.row.col.f32.bf16.bf16.f32 "
        "{%0,%1,%2,%3}, {%4,%5,%6,%7}, {%8,%9}, {%0,%1,%2,%3};\n"
        : "+f"(c0), "+f"(c1), "+f"(c2), "+f"(c3)
        : "r"(a0), "r"(a1), "r"(a2), "r"(a3), "r"(b0), "r"(b1));
}

// ----------------------------------------------------------------------------
// bf16 tensor-core GEMM body: C[128,64] = A[128,K](row-major) @ B[K,64](row-major)
// 256 threads / 8 warps; warp grid 4x2, warp tile 32x32; BK=32.
// OUT_BF16: write bf16 to Cb; else fp32 to Cf with residual add.
// ----------------------------------------------------------------------------
template<bool OUT_BF16>
__device__ __forceinline__ void mma_gemm_128x64(
        const __nv_bfloat16* __restrict__ A, int lda,
        const __nv_bfloat16* __restrict__ B, int ldb, int K,
        float* __restrict__ Cf, __nv_bfloat16* __restrict__ Cb, int ldc,
        const float* __restrict__ Res) {
    __shared__ __nv_bfloat16 As[128 * 40];   // [m][k], stride 40 halves (80B, 16B-mult)
    __shared__ __nv_bfloat16 Bs[32 * 72];    // [k][n], stride 72 halves (144B, 16B-mult)
    const int tid = threadIdx.x;
    const int lane = tid & 31, w = tid >> 5;
    const int wm = w >> 1, wn = w & 1;       // 4x2 warp grid

    float c[2][4][4];
#pragma unroll
    for (int mi = 0; mi < 2; mi++)
#pragma unroll
        for (int ni = 0; ni < 4; ni++)
#pragma unroll
            for (int r = 0; r < 4; r++) c[mi][ni][r] = 0.f;

    const int arow = tid >> 2, aq = tid & 3;      // A: 2x(64 rows x 8-half seg)
    const int brow = tid >> 3, bseg = tid & 7;    // B: 32 rows x 8x(8-half seg)

    uint4 pa0 = *(const uint4*)&A[(long)arow * lda + 8 * aq];
    uint4 pa1 = *(const uint4*)&A[(long)(arow + 64) * lda + 8 * aq];
    uint4 pb  = *(const uint4*)&B[(long)brow * ldb + 8 * bseg];

    for (int k0 = 0; k0 < K; k0 += 32) {
        __syncthreads();
        *(uint4*)&As[arow * 40 + 8 * aq] = pa0;
        *(uint4*)&As[(arow + 64) * 40 + 8 * aq] = pa1;
        *(uint4*)&Bs[brow * 72 + 8 * bseg] = pb;
        __syncthreads();
        if (k0 + 32 < K) {
            pa0 = *(const uint4*)&A[(long)arow * lda + k0 + 32 + 8 * aq];
            pa1 = *(const uint4*)&A[(long)(arow + 64) * lda + k0 + 32 + 8 * aq];
            pb  = *(const uint4*)&B[(long)(k0 + 32 + brow) * ldb + 8 * bseg];
        }
#pragma unroll
        for (int kk = 0; kk < 32; kk += 16) {
            uint32_t a[2][4];
#pragma unroll
            for (int mi = 0; mi < 2; mi++) {
                uint32_t addr = smem_u32(&As[(32 * wm + 16 * mi + (lane & 15)) * 40 + kk + ((lane >> 4) << 3)]);
                ldsm_x4(a[mi][0], a[mi][1], a[mi][2], a[mi][3], addr);
            }
            uint32_t bf[2][4];
#pragma unroll
            for (int nb = 0; nb < 2; nb++) {
                uint32_t addr = smem_u32(&Bs[(kk + (lane & 15)) * 72 + 32 * wn + 16 * nb + ((lane >> 4) << 3)]);
                ldsm_x4_t(bf[nb][0], bf[nb][1], bf[nb][2], bf[nb][3], addr);
            }
#pragma unroll
            for (int mi = 0; mi < 2; mi++)
#pragma unroll
                for (int ni = 0; ni < 4; ni++) {
                    int nb = ni >> 1, h2 = (ni & 1) * 2;
                    mma_bf16(c[mi][ni][0], c[mi][ni][1], c[mi][ni][2], c[mi][ni][3],
                             a[mi][0], a[mi][1], a[mi][2], a[mi][3], bf[nb][h2], bf[nb][h2 + 1]);
                }
        }
    }

#pragma unroll
    for (int mi = 0; mi < 2; mi++)
#pragma unroll
        for (int ni = 0; ni < 4; ni++) {
            int r = 32 * wm + 16 * mi + (lane >> 2);
            int cc = 32 * wn + 8 * ni + (lane & 3) * 2;
            if (OUT_BF16) {
                *(__nv_bfloat162*)&Cb[(long)r * ldc + cc] =
                    __float22bfloat162_rn(make_float2(c[mi][ni][0], c[mi][ni][1]));
                *(__nv_bfloat162*)&Cb[(long)(r + 8) * ldc + cc] =
                    __float22bfloat162_rn(make_float2(c[mi][ni][2], c[mi][ni][3]));
            } else {
                float2 r0 = *(const float2*)&Res[(long)r * ldc + cc];
                float2 r1 = *(const float2*)&Res[(long)(r + 8) * ldc + cc];
                *(float2*)&Cf[(long)r * ldc + cc] = make_float2(c[mi][ni][0] + r0.x, c[mi][ni][1] + r0.y);
                *(float2*)&Cf[(long)(r + 8) * ldc + cc] = make_float2(c[mi][ni][2] + r1.x, c[mi][ni][3] + r1.y);
            }
        }
}

// attn(bf16) @ V(bf16) -> ctx(bf16). grid (S/128, B*H)
__global__ __launch_bounds__(256) void av_mma(const __nv_bfloat16* __restrict__ attnb,
                                              const __nv_bfloat16* __restrict__ Vb,
                                              __nv_bfloat16* __restrict__ ctxb) {
    const int z = blockIdx.y, b = z >> 3, h = z & 7;
    const int q0 = blockIdx.x * 128;
    mma_gemm_128x64<true>(attnb + (long)z * SS * SS + (long)q0 * SS, SS,
                          Vb + (long)b * SS * DD + h * 64, DD, SS,
                          nullptr, ctxb + (long)b * SS * DD + (long)q0 * DD + h * 64, DD, nullptr);
}

// ctx(bf16) @ w_fc(bf16) + residual -> out(f32). grid (D/64, ROWS/128)
__global__ __launch_bounds__(256) void fc_mma(const __nv_bfloat16* __restrict__ ctxb,
                                              const __nv_bfloat16* __restrict__ wfcb,
                                              const float* __restrict__ res,
                                              float* __restrict__ out) {
    const int bn = blockIdx.x * 64;
    const long bm = (long)blockIdx.y * 128;
    mma_gemm_128x64<false>(ctxb + bm * DD, DD, wfcb + bn, DD, DD,
                           out + bm * DD + bn, nullptr, DD, res + bm * DD + bn);
}

__global__ void cvt_wfc(const float* __restrict__ w, __nv_bfloat16* __restrict__ o) {
    int i = blockIdx.x * 256 + threadIdx.x;       // 131072 threads x 2 elems
    float2 v = *(const float2*)&w[2 * i];
    *(__nv_bfloat162*)&o[2 * i] = __float22bfloat162_rn(v);
}

// ----------------------------------------------------------------------------
// fp32 GEMM (projections): C = A @ B. BM=BN=128, BK=16, 8x8 micro, reg prefetch.
// outbf: write bf16 (V projection) instead of fp32.
// ----------------------------------------------------------------------------
__device__ __forceinline__ void gemm_f32_body(const float* __restrict__ A,
                                              const float* __restrict__ B,
                                              float* __restrict__ Cf,
                                              __nv_bfloat16* __restrict__ Cb, bool outbf,
                                              int K, int lda, int ldb, int ldc,
                                              int bm, int bn) {
    __shared__ float As[16 * 132];
    __shared__ float Bs[16 * 128];
    const int tid = threadIdx.x;
    const int ty = tid >> 4, tx = tid & 15;

    float acc[8][8];
#pragma unroll
    for (int i = 0; i < 8; i++)
#pragma unroll
        for (int j = 0; j < 8; j++) acc[i][j] = 0.f;

    const int fA = tid & 3, rA = tid >> 2;
    const int cB = tid & 31, kB = tid >> 5;

    float4 pa0 = *(const float4*)&A[(long)(bm + rA) * lda + 4 * fA];
    float4 pa1 = *(const float4*)&A[(long)(bm + rA + 64) * lda + 4 * fA];
    float4 pb0 = *(const float4*)&B[(long)kB * ldb + bn + 4 * cB];
    float4 pb1 = *(const float4*)&B[(long)(kB + 8) * ldb + bn + 4 * cB];

    for (int k0 = 0; k0 < K; k0 += 16) {
        __syncthreads();
        As[(4 * fA + 0) * 132 + rA] = pa0.x;
        As[(4 * fA + 1) * 132 + rA] = pa0.y;
        As[(4 * fA + 2) * 132 + rA] = pa0.z;
        As[(4 * fA + 3) * 132 + rA] = pa0.w;
        As[(4 * fA + 0) * 132 + rA + 64] = pa1.x;
        As[(4 * fA + 1) * 132 + rA + 64] = pa1.y;
        As[(4 * fA + 2) * 132 + rA + 64] = pa1.z;
        As[(4 * fA + 3) * 132 + rA + 64] = pa1.w;
        *(float4*)&Bs[kB * 128 + 4 * cB] = pb0;
        *(float4*)&Bs[(kB + 8) * 128 + 4 * cB] = pb1;
        __syncthreads();
        if (k0 + 16 < K) {
            pa0 = *(const float4*)&A[(long)(bm + rA) * lda + k0 + 16 + 4 * fA];
            pa1 = *(const float4*)&A[(long)(bm + rA + 64) * lda + k0 + 16 + 4 * fA];
            pb0 = *(const float4*)&B[(long)(k0 + 16 + kB) * ldb + bn + 4 * cB];
            pb1 = *(const float4*)&B[(long)(k0 + 24 + kB) * ldb + bn + 4 * cB];
        }
#pragma unroll
        for (int kk = 0; kk < 16; kk++) {
            float4 a0 = *(const float4*)&As[kk * 132 + 8 * ty];
            float4 a1 = *(const float4*)&As[kk * 132 + 8 * ty + 4];
            float4 b0 = *(const float4*)&Bs[kk * 128 + 8 * tx];
            float4 b1 = *(const float4*)&Bs[kk * 128 + 8 * tx + 4];
            float a[8] = {a0.x, a0.y, a0.z, a0.w, a1.x, a1.y, a1.z, a1.w};
            float b[8] = {b0.x, b0.y, b0.z, b0.w, b1.x, b1.y, b1.z, b1.w};
#pragma unroll
            for (int i = 0; i < 8; i++)
#pragma unroll
                for (int j = 0; j < 8; j++) acc[i][j] += a[i] * b[j];
        }
    }

#pragma unroll
    for (int i = 0; i < 8; i++) {
        long r = bm + 8 * ty + i;
        if (outbf) {
#pragma unroll
            for (int jj = 0; jj < 4; jj++) {
                long cc = bn + 8 * tx + 2 * jj;
                *(__nv_bfloat162*)&Cb[r * ldc + cc] =
                    __float22bfloat162_rn(make_float2(acc[i][2 * jj], acc[i][2 * jj + 1]));
            }
        } else {
#pragma unroll
            for (int jj = 0; jj < 2; jj++) {
                long cc = bn + 8 * tx + 4 * jj;
                *(float4*)&Cf[r * ldc + cc] =
                    make_float4(acc[i][4 * jj], acc[i][4 * jj + 1], acc[i][4 * jj + 2], acc[i][4 * jj + 3]);
            }
        }
    }
}

// Fused Q/K/V projections; V writes bf16.
__global__ __launch_bounds__(256) void proj3_kernel(
        const float* __restrict__ Aq, const float* __restrict__ Ak, const float* __restrict__ Av,
        const float* __restrict__ Wq, const float* __restrict__ Wk, const float* __restrict__ Wv,
        float* __restrict__ Cq, float* __restrict__ Ck, __nv_bfloat16* __restrict__ Cvb) {
    const int z = blockIdx.z;
    const float* A = (z == 0) ? Aq : (z == 1) ? Ak : Av;
    const float* B = (z == 0) ? Wq : (z == 1) ? Wk : Wv;
    float* Cf = (z == 0) ? Cq : Ck;
    gemm_f32_body(A, B, Cf, Cvb, z == 2, DD, DD, DD, DD, blockIdx.y * 128, blockIdx.x * 128);
}

// ----------------------------------------------------------------------------
// Scores + bias. Block = (k-tile 64, q-tile 64, batch). 256 threads. fp32.
// ----------------------------------------------------------------------------
__global__ __launch_bounds__(256) void scores_kernel(
        const float* __restrict__ Qp, const float* __restrict__ Kp,
        const int* __restrict__ attn_if, const int* __restrict__ itype,
        const float* __restrict__ im, const float* __restrict__ type_emb,
        const float* __restrict__ w_feat, float* __restrict__ attn_out) {
    extern __shared__ char smraw[];
    float* Qt = (float*)smraw;                       // 64 d x 68
    float* Kt = Qt + 64 * 68;
    __nv_bfloat16* biasS = (__nv_bfloat16*)(Kt + 64 * 68);  // 8*64*64

    const int b = blockIdx.z;
    const int q0 = blockIdx.y * 64;
    const int k0 = blockIdx.x * 64;
    const int tid = threadIdx.x;

    __shared__ float wf[6][8];
    if (tid < 48) wf[tid / 8][tid % 8] = w_feat[tid];
    __syncthreads();

#pragma unroll
    for (int l = 0; l < 16; l++) {
        int idx = tid + l * 256;
        int qi = idx >> 6, ki = idx & 63;
        long pair = ((long)(b * SS + q0 + qi)) * SS + (k0 + ki);
        if (attn_if[pair] != 0) {
#pragma unroll
            for (int h = 0; h < 8; h++)
                biasS[h * 4096 + qi * 64 + ki] = __float2bfloat16(NEGV);
        } else {
            int t = itype[pair];
            const float* e = type_emb + (long)t * 8;
            const float2* imp = (const float2*)(im + pair * 6);
            float2 p0 = imp[0], p1 = imp[1], p2 = imp[2];
#pragma unroll
            for (int h = 0; h < 8; h++) {
                float s = p0.x * wf[0][h] + p0.y * wf[1][h] + p1.x * wf[2][h]
                        + p1.y * wf[3][h] + p2.x * wf[4][h] + p2.y * wf[5][h];
                s = fmaxf(s, 0.f) + e[h];
                biasS[h * 4096 + qi * 64 + ki] = __float2bfloat16(s);
            }
        }
    }

    const int ty = tid >> 4, tx = tid & 15;
    const int fL = tid & 15, rL = tid >> 4;

    for (int h = 0; h < 8; h++) {
        __syncthreads();
#pragma unroll
        for (int l = 0; l < 4; l++) {
            int r = rL + l * 16;
            float4 q = *(const float4*)&Qp[((long)(b * SS + q0 + r)) * DD + h * 64 + 4 * fL];
            float4 k = *(const float4*)&Kp[((long)(b * SS + k0 + r)) * DD + h * 64 + 4 * fL];
            Qt[(4 * fL + 0) * 68 + r] = q.x;  Kt[(4 * fL + 0) * 68 + r] = k.x;
            Qt[(4 * fL + 1) * 68 + r] = q.y;  Kt[(4 * fL + 1) * 68 + r] = k.y;
            Qt[(4 * fL + 2) * 68 + r] = q.z;  Kt[(4 * fL + 2) * 68 + r] = k.z;
            Qt[(4 * fL + 3) * 68 + r] = q.w;  Kt[(4 * fL + 3) * 68 + r] = k.w;
        }
        __syncthreads();

        float acc[4][4];
#pragma unroll
        for (int i = 0; i < 4; i++)
#pragma unroll
            for (int j = 0; j < 4; j++) acc[i][j] = 0.f;

#pragma unroll
        for (int d = 0; d < 64; d++) {
            float4 a4 = *(const float4*)&Qt[d * 68 + 4 * ty];
            float4 b4 = *(const float4*)&Kt[d * 68 + 4 * tx];
            float a[4] = {a4.x, a4.y, a4.z, a4.w};
            float bb[4] = {b4.x, b4.y, b4.z, b4.w};
#pragma unroll
            for (int i = 0; i < 4; i++)
#pragma unroll
                for (int j = 0; j < 4; j++) acc[i][j] += a[i] * bb[j];
        }

        float* outp = attn_out + (((long)(b * HH + h) * SS + q0)) * SS + k0;
#pragma unroll
        for (int i = 0; i < 4; i++) {
            int qi = 4 * ty + i;
            const __nv_bfloat16* bp = &biasS[h * 4096 + qi * 64 + 4 * tx];
            float4 v;
            v.x = acc[i][0] * 0.125f + __bfloat162float(bp[0]);
            v.y = acc[i][1] * 0.125f + __bfloat162float(bp[1]);
            v.z = acc[i][2] * 0.125f + __bfloat162float(bp[2]);
            v.w = acc[i][3] * 0.125f + __bfloat162float(bp[3]);
            *(float4*)&outp[(long)qi * SS + 4 * tx] = v;
        }
    }
}

// ----------------------------------------------------------------------------
// Row softmax, contiguous float4 per thread; writes f32 (output) + bf16 copy.
// ----------------------------------------------------------------------------
__global__ void softmax_kernel(float* __restrict__ attn, __nv_bfloat16* __restrict__ attnb) {
    const long row = blockIdx.x;
    float* p = attn + row * SS;
    const int tid = threadIdx.x;
    float4 v = *(const float4*)&p[tid * 4];
    float mx = fmaxf(fmaxf(v.x, v.y), fmaxf(v.z, v.w));
#pragma unroll
    for (int o = 16; o; o >>= 1) mx = fmaxf(mx, __shfl_xor_sync(0xffffffffu, mx, o));
    __shared__ float rmx[8], rsm[8];
    if ((tid & 31) == 0) rmx[tid >> 5] = mx;
    __syncthreads();
    float bm = rmx[0];
#pragma unroll
    for (int w = 1; w < 8; w++) bm = fmaxf(bm, rmx[w]);
    v.x = __expf(v.x - bm); v.y = __expf(v.y - bm);
    v.z = __expf(v.z - bm); v.w = __expf(v.w - bm);
    float s = v.x + v.y + v.z + v.w;
#pragma unroll
    for (int o = 16; o; o >>= 1) s += __shfl_xor_sync(0xffffffffu, s, o);
    if ((tid & 31) == 0) rsm[tid >> 5] = s;
    __syncthreads();
    float tot = 0.f;
#pragma unroll
    for (int w = 0; w < 8; w++) tot += rsm[w];
    float inv = 1.f / tot;
    v.x *= inv; v.y *= inv; v.z *= inv; v.w *= inv;
    *(float4*)&p[tid * 4] = v;
    __nv_bfloat162* pb = (__nv_bfloat162*)(attnb + row * SS);
    pb[tid * 2 + 0] = __float22bfloat162_rn(make_float2(v.x, v.y));
    pb[tid * 2 + 1] = __float22bfloat162_rn(make_float2(v.z, v.w));
}

// ----------------------------------------------------------------------------
// In-place LayerNorm over last dim (512). grid = ROWS, 256 threads.
// ----------------------------------------------------------------------------
__global__ void ln_kernel(float* __restrict__ out, const float* __restrict__ g,
                          const float* __restrict__ bta) {
    const long row = blockIdx.x;
    float* p = out + row * DD;
    const int tid = threadIdx.x;
    float x0 = p[tid], x1 = p[tid + 256];
    float s = x0 + x1, ss = x0 * x0 + x1 * x1;
#pragma unroll
    for (int o = 16; o; o >>= 1) {
        s += __shfl_xor_sync(0xffffffffu, s, o);
        ss += __shfl_xor_sync(0xffffffffu, ss, o);
    }
    __shared__ float rs[8], rss[8];
    if ((tid & 31) == 0) { rs[tid >> 5] = s; rss[tid >> 5] = ss; }
    __syncthreads();
    float S = 0.f, SSq = 0.f;
#pragma unroll
    for (int w = 0; w < 8; w++) { S += rs[w]; SSq += rss[w]; }
    float mu = S * (1.f / 512.f);
    float var = SSq * (1.f / 512.f) - mu * mu;
    float inv = rsqrtf(var + 1e-5f);
    p[tid] = (x0 - mu) * inv * g[tid] + bta[tid];
    p[tid + 256] = (x1 - mu) * inv * g[tid + 256] + bta[tid + 256];
}

// ----------------------------------------------------------------------------
extern "C" void kernel_launch(void* const* d_in, const int* in_sizes, int n_in,
                              void* d_out, int out_size) {
    const float* input_Q = (const float*)d_in[0];
    const float* input_K = (const float*)d_in[1];
    const float* input_V = (const float*)d_in[2];
    const int* attn_if = (const int*)d_in[4];
    const int* itype = (const int*)d_in[5];
    const float* im = (const float*)d_in[6];
    const float* w_q = (const float*)d_in[9];
    const float* w_k = (const float*)d_in[10];
    const float* w_v = (const float*)d_in[11];
    const float* w_fc = (const float*)d_in[12];
    const float* ln_g = (const float*)d_in[13];
    const float* ln_b = (const float*)d_in[14];
    const float* type_emb = (const float*)d_in[15];
    const float* w_feat = (const float*)d_in[16];

    float* out = (float*)d_out;
    float* attn = out + (size_t)ROWS * DD;

    float *Qp, *Kp;
    __nv_bfloat16 *Vpb, *ctxb, *attnb, *wfcb;
    cudaGetSymbolAddress((void**)&Qp, g_Qp);
    cudaGetSymbolAddress((void**)&Kp, g_Kp);
    cudaGetSymbolAddress((void**)&Vpb, g_Vpb);
    cudaGetSymbolAddress((void**)&ctxb, g_ctxb);
    cudaGetSymbolAddress((void**)&attnb, g_attnb);
    cudaGetSymbolAddress((void**)&wfcb, g_wfcb);

    // w_fc -> bf16 (runs concurrently with projections)
    cvt_wfc<<<DD * DD / 512, 256>>>(w_fc, wfcb);

    // Fused projections: Q,K fp32; V bf16
    dim3 gproj(DD / 128, ROWS / 128, 3);
    proj3_kernel<<<gproj, 256>>>(input_Q, input_K, input_V, w_q, w_k, w_v, Qp, Kp, Vpb);

    // Scores + bias -> attn region (raw)
    size_t smem = (size_t)(2 * 64 * 68) * sizeof(float) + (size_t)8 * 64 * 64 * sizeof(__nv_bfloat16);
    cudaFuncSetAttribute(scores_kernel, cudaFuncAttributeMaxDynamicSharedMemorySize, (int)smem);
    dim3 gsc(SS / 64, SS / 64, BB);
    scores_kernel<<<gsc, 256, smem>>>(Qp, Kp, attn_if, itype, im, type_emb, w_feat, attn);

    // Softmax in place + bf16 copy
    softmax_kernel<<<BB * HH * SS, 256>>>(attn, attnb);

    // attn @ V -> ctx (bf16 MMA)
    dim3 gav(SS / 128, BB * HH);
    av_mma<<<gav, 256>>>(attnb, Vpb, ctxb);

    // FC + residual -> out (bf16 MMA)
    dim3 gfc(DD / 64, ROWS / 128);
    fc_mma<<<gfc, 256>>>(ctxb, wfcb, input_Q, out);

    // LayerNorm in place
    ln_kernel<<<ROWS, 256>>>(out, ln_g, ln_b);
}

// round 7
// speedup vs baseline: 2.1047x; 1.4979x over previous
#include <cuda_runtime.h>
#include <cuda_bf16.h>
#include <math.h>
#include <stdint.h>

// Problem constants
#define BB 4
#define SS 1024
#define DD 512
#define HH 8
#define ROWS (BB*SS)          // 4096
#define NEGV (-1e9f)

// Scratch (device globals; no allocation allowed)
__device__ float g_Qp[ROWS*DD];
__device__ float g_Kp[ROWS*DD];
__device__ __nv_bfloat16 g_Vpb[ROWS*DD];
__device__ __nv_bfloat16 g_ctxb[ROWS*DD];
__device__ __nv_bfloat16 g_attnb[BB*HH*SS*SS];
__device__ __nv_bfloat16 g_wfcb[DD*DD];

// ============================ MMA helpers ===================================
__device__ __forceinline__ uint32_t smem_u32(const void* p) {
    return (uint32_t)__cvta_generic_to_shared(p);
}
__device__ __forceinline__ uint32_t f2tf32(float f) {
    uint32_t r; asm("cvt.rna.tf32.f32 %0, %1;" : "=r"(r) : "f"(f)); return r;
}
__device__ __forceinline__ void mma_tf32(float& c0, float& c1, float& c2, float& c3,
        uint32_t a0, uint32_t a1, uint32_t a2, uint32_t a3, uint32_t b0, uint32_t b1) {
    asm volatile("mma.sync.aligned.m16n8k8.row.col.f32.tf32.tf32.f32 "
        "{%0,%1,%2,%3}, {%4,%5,%6,%7}, {%8,%9}, {%0,%1,%2,%3};\n"
        : "+f"(c0), "+f"(c1), "+f"(c2), "+f"(c3)
        : "r"(a0), "r"(a1), "r"(a2), "r"(a3), "r"(b0), "r"(b1));
}
__device__ __forceinline__ void ldsm_x4(uint32_t& r0, uint32_t& r1, uint32_t& r2, uint32_t& r3, uint32_t addr) {
    asm volatile("ldmatrix.sync.aligned.m8n8.x4.shared.b16 {%0,%1,%2,%3}, [%4];\n"
        : "=r"(r0), "=r"(r1), "=r"(r2), "=r"(r3) : "r"(addr));
}
__device__ __forceinline__ void ldsm_x4_t(uint32_t& r0, uint32_t& r1, uint32_t& r2, uint32_t& r3, uint32_t addr) {
    asm volatile("ldmatrix.sync.aligned.m8n8.x4.trans.shared.b16 {%0,%1,%2,%3}, [%4];\n"
        : "=r"(r0), "=r"(r1), "=r"(r2), "=r"(r3) : "r"(addr));
}
__device__ __forceinline__ void mma_bf16(float& c0, float& c1, float& c2, float& c3,
        uint32_t a0, uint32_t a1, uint32_t a2, uint32_t a3, uint32_t b0, uint32_t b1) {
    asm volatile("mma.sync.aligned.m16n8k16.row.col.f32.bf16.bf16.f32 "
        "{%0,%1,%2,%3}, {%4,%5,%6,%7}, {%8,%9}, {%0,%1,%2,%3};\n"
        : "+f"(c0), "+f"(c1), "+f"(c2), "+f"(c3)
        : "r"(a0), "r"(a1), "r"(a2), "r"(a3), "r"(b0), "r"(b1));
}

// ----------------------------------------------------------------------------
// tf32 GEMM: C[128,128] = A[.,K]f32 @ B[K,.]f32, BK=16, 256 thr / 8 warps,
// warp grid 4x2 (warp tile 32x64). OUT_BF16 selects bf16 output (V proj).
// ----------------------------------------------------------------------------
template<bool OUT_BF16>
__device__ __forceinline__ void tf32_gemm_128x128(
        const float* __restrict__ A, const float* __restrict__ B,
        float* __restrict__ Cf, __nv_bfloat16* __restrict__ Cb,
        int K, int lda, int ldb, int ldc, int bm, int bn) {
    __shared__ uint32_t As[128 * 20];    // [m][k], stride 20 (80B, 16B-mult)
    __shared__ uint32_t Bs[16 * 132];    // [k][n], stride 132 (528B, 16B-mult)
    const int tid = threadIdx.x;
    const int lane = tid & 31, w = tid >> 5;
    const int wm = w >> 1, wn = w & 1;
    const int g = lane >> 2, t = lane & 3;

    float acc[2][8][4];
#pragma unroll
    for (int mi = 0; mi < 2; mi++)
#pragma unroll
        for (int ni = 0; ni < 8; ni++)
#pragma unroll
            for (int r = 0; r < 4; r++) acc[mi][ni][r] = 0.f;

    const int rA = tid >> 2, fA = tid & 3;     // A: rows {rA, rA+64}, col 4fA
    const int kB = tid >> 5, cB = tid & 31;    // B: rows {kB, kB+8}, col 4cB

    float4 pa0 = *(const float4*)&A[(long)(bm + rA) * lda + 4 * fA];
    float4 pa1 = *(const float4*)&A[(long)(bm + rA + 64) * lda + 4 * fA];
    float4 pb0 = *(const float4*)&B[(long)kB * ldb + bn + 4 * cB];
    float4 pb1 = *(const float4*)&B[(long)(kB + 8) * ldb + bn + 4 * cB];

    for (int k0 = 0; k0 < K; k0 += 16) {
        __syncthreads();
        {
            uint4 v0 = make_uint4(f2tf32(pa0.x), f2tf32(pa0.y), f2tf32(pa0.z), f2tf32(pa0.w));
            uint4 v1 = make_uint4(f2tf32(pa1.x), f2tf32(pa1.y), f2tf32(pa1.z), f2tf32(pa1.w));
            *(uint4*)&As[rA * 20 + 4 * fA] = v0;
            *(uint4*)&As[(rA + 64) * 20 + 4 * fA] = v1;
            uint4 w0 = make_uint4(f2tf32(pb0.x), f2tf32(pb0.y), f2tf32(pb0.z), f2tf32(pb0.w));
            uint4 w1 = make_uint4(f2tf32(pb1.x), f2tf32(pb1.y), f2tf32(pb1.z), f2tf32(pb1.w));
            *(uint4*)&Bs[kB * 132 + 4 * cB] = w0;
            *(uint4*)&Bs[(kB + 8) * 132 + 4 * cB] = w1;
        }
        __syncthreads();
        if (k0 + 16 < K) {
            pa0 = *(const float4*)&A[(long)(bm + rA) * lda + k0 + 16 + 4 * fA];
            pa1 = *(const float4*)&A[(long)(bm + rA + 64) * lda + k0 + 16 + 4 * fA];
            pb0 = *(const float4*)&B[(long)(k0 + 16 + kB) * ldb + bn + 4 * cB];
            pb1 = *(const float4*)&B[(long)(k0 + 24 + kB) * ldb + bn + 4 * cB];
        }
#pragma unroll
        for (int ks = 0; ks < 16; ks += 8) {
            uint32_t a[2][4];
#pragma unroll
            for (int mi = 0; mi < 2; mi++) {
                int rb = (32 * wm + 16 * mi + g) * 20 + ks + t;
                a[mi][0] = As[rb];
                a[mi][1] = As[rb + 8 * 20];
                a[mi][2] = As[rb + 4];
                a[mi][3] = As[rb + 8 * 20 + 4];
            }
            uint32_t bb[8][2];
#pragma unroll
            for (int ni = 0; ni < 8; ni++) {
                int nb = 64 * wn + 8 * ni + g;
                bb[ni][0] = Bs[(ks + t) * 132 + nb];
                bb[ni][1] = Bs[(ks + t + 4) * 132 + nb];
            }
#pragma unroll
            for (int mi = 0; mi < 2; mi++)
#pragma unroll
                for (int ni = 0; ni < 8; ni++)
                    mma_tf32(acc[mi][ni][0], acc[mi][ni][1], acc[mi][ni][2], acc[mi][ni][3],
                             a[mi][0], a[mi][1], a[mi][2], a[mi][3], bb[ni][0], bb[ni][1]);
        }
    }

#pragma unroll
    for (int mi = 0; mi < 2; mi++)
#pragma unroll
        for (int ni = 0; ni < 8; ni++) {
            long r0 = bm + 32 * wm + 16 * mi + g;
            long cc = bn + 64 * wn + 8 * ni + 2 * t;
            if (OUT_BF16) {
                *(__nv_bfloat162*)&Cb[r0 * ldc + cc] =
                    __float22bfloat162_rn(make_float2(acc[mi][ni][0], acc[mi][ni][1]));
                *(__nv_bfloat162*)&Cb[(r0 + 8) * ldc + cc] =
                    __float22bfloat162_rn(make_float2(acc[mi][ni][2], acc[mi][ni][3]));
            } else {
                *(float2*)&Cf[r0 * ldc + cc] = make_float2(acc[mi][ni][0], acc[mi][ni][1]);
                *(float2*)&Cf[(r0 + 8) * ldc + cc] = make_float2(acc[mi][ni][2], acc[mi][ni][3]);
            }
        }
}

// Fused Q/K/V projections; V writes bf16.
__global__ __launch_bounds__(256) void proj3_kernel(
        const float* __restrict__ Aq, const float* __restrict__ Ak, const float* __restrict__ Av,
        const float* __restrict__ Wq, const float* __restrict__ Wk, const float* __restrict__ Wv,
        float* __restrict__ Cq, float* __restrict__ Ck, __nv_bfloat16* __restrict__ Cvb) {
    const int z = blockIdx.z;
    const float* A = (z == 0) ? Aq : (z == 1) ? Ak : Av;
    const float* B = (z == 0) ? Wq : (z == 1) ? Wk : Wv;
    if (z == 2)
        tf32_gemm_128x128<true>(A, B, nullptr, Cvb, DD, DD, DD, DD, blockIdx.y * 128, blockIdx.x * 128);
    else
        tf32_gemm_128x128<false>(A, B, (z == 0) ? Cq : Ck, nullptr, DD, DD, DD, DD, blockIdx.y * 128, blockIdx.x * 128);
}

// ----------------------------------------------------------------------------
// Scores + bias. Block = (k-tile 64, q-tile 64, batch). 256 threads.
// QK^T via tf32 MMA; bias[8][64][64] bf16 computed once for all heads.
// ----------------------------------------------------------------------------
__global__ __launch_bounds__(256) void scores_kernel(
        const float* __restrict__ Qp, const float* __restrict__ Kp,
        const int* __restrict__ attn_if, const int* __restrict__ itype,
        const float* __restrict__ im, const float* __restrict__ type_emb,
        const float* __restrict__ w_feat, float* __restrict__ attn_out) {
    extern __shared__ char smraw[];
    uint32_t* Qt = (uint32_t*)smraw;                 // [64 q][68] tf32
    uint32_t* Kt = Qt + 64 * 68;                     // [64 k][68] tf32
    __nv_bfloat16* biasS = (__nv_bfloat16*)(Kt + 64 * 68);  // 8*64*64

    const int b = blockIdx.z;
    const int q0 = blockIdx.y * 64;
    const int k0 = blockIdx.x * 64;
    const int tid = threadIdx.x;
    const int lane = tid & 31, w = tid >> 5;
    const int wm = w >> 1, wn = w & 1;               // 4x2 warp grid, tile m16 x n32
    const int g = lane >> 2, t = lane & 3;

    __shared__ float wf[6][8];
    if (tid < 48) wf[tid / 8][tid % 8] = w_feat[tid];
    __syncthreads();

    // Per-pair bias for all 8 heads (computed once).
#pragma unroll
    for (int l = 0; l < 16; l++) {
        int idx = tid + l * 256;
        int qi = idx >> 6, ki = idx & 63;
        long pair = ((long)(b * SS + q0 + qi)) * SS + (k0 + ki);
        if (attn_if[pair] != 0) {
#pragma unroll
            for (int h = 0; h < 8; h++)
                biasS[h * 4096 + qi * 64 + ki] = __float2bfloat16(NEGV);
        } else {
            int tt = itype[pair];
            const float* e = type_emb + (long)tt * 8;
            const float2* imp = (const float2*)(im + pair * 6);
            float2 p0 = imp[0], p1 = imp[1], p2 = imp[2];
#pragma unroll
            for (int h = 0; h < 8; h++) {
                float s = p0.x * wf[0][h] + p0.y * wf[1][h] + p1.x * wf[2][h]
                        + p1.y * wf[3][h] + p2.x * wf[4][h] + p2.y * wf[5][h];
                s = fmaxf(s, 0.f) + e[h];
                biasS[h * 4096 + qi * 64 + ki] = __float2bfloat16(s);
            }
        }
    }

    const int fL = tid & 15, rL = tid >> 4;

    for (int h = 0; h < 8; h++) {
        __syncthreads();
        // Stage Q/K tiles (row-major [row][d]) with tf32 rounding
#pragma unroll
        for (int l = 0; l < 4; l++) {
            int r = rL + l * 16;
            float4 q = *(const float4*)&Qp[((long)(b * SS + q0 + r)) * DD + h * 64 + 4 * fL];
            float4 k = *(const float4*)&Kp[((long)(b * SS + k0 + r)) * DD + h * 64 + 4 * fL];
            *(uint4*)&Qt[r * 68 + 4 * fL] = make_uint4(f2tf32(q.x), f2tf32(q.y), f2tf32(q.z), f2tf32(q.w));
            *(uint4*)&Kt[r * 68 + 4 * fL] = make_uint4(f2tf32(k.x), f2tf32(k.y), f2tf32(k.z), f2tf32(k.w));
        }
        __syncthreads();

        float acc[4][4];
#pragma unroll
        for (int ni = 0; ni < 4; ni++)
#pragma unroll
            for (int r = 0; r < 4; r++) acc[ni][r] = 0.f;

#pragma unroll
        for (int k8 = 0; k8 < 64; k8 += 8) {
            int rb = (16 * wm + g) * 68 + k8 + t;
            uint32_t a0 = Qt[rb];
            uint32_t a1 = Qt[rb + 8 * 68];
            uint32_t a2 = Qt[rb + 4];
            uint32_t a3 = Qt[rb + 8 * 68 + 4];
#pragma unroll
            for (int ni = 0; ni < 4; ni++) {
                int nb = (32 * wn + 8 * ni + g) * 68 + k8 + t;
                uint32_t b0 = Kt[nb];
                uint32_t b1 = Kt[nb + 4];
                mma_tf32(acc[ni][0], acc[ni][1], acc[ni][2], acc[ni][3], a0, a1, a2, a3, b0, b1);
            }
        }

        float* outp = attn_out + (((long)(b * HH + h) * SS + q0)) * SS + k0;
#pragma unroll
        for (int ni = 0; ni < 4; ni++) {
            int row0 = 16 * wm + g;
            int col = 32 * wn + 8 * ni + 2 * t;
            __nv_bfloat162 bA = *(const __nv_bfloat162*)&biasS[h * 4096 + row0 * 64 + col];
            __nv_bfloat162 bB = *(const __nv_bfloat162*)&biasS[h * 4096 + (row0 + 8) * 64 + col];
            *(float2*)&outp[(long)row0 * SS + col] =
                make_float2(acc[ni][0] * 0.125f + __bfloat162float(bA.x),
                            acc[ni][1] * 0.125f + __bfloat162float(bA.y));
            *(float2*)&outp[(long)(row0 + 8) * SS + col] =
                make_float2(acc[ni][2] * 0.125f + __bfloat162float(bB.x),
                            acc[ni][3] * 0.125f + __bfloat162float(bB.y));
        }
    }
}

// ----------------------------------------------------------------------------
// bf16 tensor-core GEMM body: C[128,64] = A[128,K] @ B[K,64] (both row-major)
// ----------------------------------------------------------------------------
template<bool OUT_BF16>
__device__ __forceinline__ void mma_gemm_128x64(
        const __nv_bfloat16* __restrict__ A, int lda,
        const __nv_bfloat16* __restrict__ B, int ldb, int K,
        float* __restrict__ Cf, __nv_bfloat16* __restrict__ Cb, int ldc,
        const float* __restrict__ Res) {
    __shared__ __nv_bfloat16 As[128 * 40];
    __shared__ __nv_bfloat16 Bs[32 * 72];
    const int tid = threadIdx.x;
    const int lane = tid & 31, w = tid >> 5;
    const int wm = w >> 1, wn = w & 1;

    float c[2][4][4];
#pragma unroll
    for (int mi = 0; mi < 2; mi++)
#pragma unroll
        for (int ni = 0; ni < 4; ni++)
#pragma unroll
            for (int r = 0; r < 4; r++) c[mi][ni][r] = 0.f;

    const int arow = tid >> 2, aq = tid & 3;
    const int brow = tid >> 3, bseg = tid & 7;

    uint4 pa0 = *(const uint4*)&A[(long)arow * lda + 8 * aq];
    uint4 pa1 = *(const uint4*)&A[(long)(arow + 64) * lda + 8 * aq];
    uint4 pb  = *(const uint4*)&B[(long)brow * ldb + 8 * bseg];

    for (int k0 = 0; k0 < K; k0 += 32) {
        __syncthreads();
        *(uint4*)&As[arow * 40 + 8 * aq] = pa0;
        *(uint4*)&As[(arow + 64) * 40 + 8 * aq] = pa1;
        *(uint4*)&Bs[brow * 72 + 8 * bseg] = pb;
        __syncthreads();
        if (k0 + 32 < K) {
            pa0 = *(const uint4*)&A[(long)arow * lda + k0 + 32 + 8 * aq];
            pa1 = *(const uint4*)&A[(long)(arow + 64) * lda + k0 + 32 + 8 * aq];
            pb  = *(const uint4*)&B[(long)(k0 + 32 + brow) * ldb + 8 * bseg];
        }
#pragma unroll
        for (int kk = 0; kk < 32; kk += 16) {
            uint32_t a[2][4];
#pragma unroll
            for (int mi = 0; mi < 2; mi++) {
                uint32_t addr = smem_u32(&As[(32 * wm + 16 * mi + (lane & 15)) * 40 + kk + ((lane >> 4) << 3)]);
                ldsm_x4(a[mi][0], a[mi][1], a[mi][2], a[mi][3], addr);
            }
            uint32_t bf[2][4];
#pragma unroll
            for (int nb = 0; nb < 2; nb++) {
                uint32_t addr = smem_u32(&Bs[(kk + (lane & 15)) * 72 + 32 * wn + 16 * nb + ((lane >> 4) << 3)]);
                ldsm_x4_t(bf[nb][0], bf[nb][1], bf[nb][2], bf[nb][3], addr);
            }
#pragma unroll
            for (int mi = 0; mi < 2; mi++)
#pragma unroll
                for (int ni = 0; ni < 4; ni++) {
                    int nb = ni >> 1, h2 = (ni & 1) * 2;
                    mma_bf16(c[mi][ni][0], c[mi][ni][1], c[mi][ni][2], c[mi][ni][3],
                             a[mi][0], a[mi][1], a[mi][2], a[mi][3], bf[nb][h2], bf[nb][h2 + 1]);
                }
        }
    }

#pragma unroll
    for (int mi = 0; mi < 2; mi++)
#pragma unroll
        for (int ni = 0; ni < 4; ni++) {
            int r = 32 * wm + 16 * mi + (lane >> 2);
            int cc = 32 * wn + 8 * ni + (lane & 3) * 2;
            if (OUT_BF16) {
                *(__nv_bfloat162*)&Cb[(long)r * ldc + cc] =
                    __float22bfloat162_rn(make_float2(c[mi][ni][0], c[mi][ni][1]));
                *(__nv_bfloat162*)&Cb[(long)(r + 8) * ldc + cc] =
                    __float22bfloat162_rn(make_float2(c[mi][ni][2], c[mi][ni][3]));
            } else {
                float2 r0 = *(const float2*)&Res[(long)r * ldc + cc];
                float2 r1 = *(const float2*)&Res[(long)(r + 8) * ldc + cc];
                *(float2*)&Cf[(long)r * ldc + cc] = make_float2(c[mi][ni][0] + r0.x, c[mi][ni][1] + r0.y);
                *(float2*)&Cf[(long)(r + 8) * ldc + cc] = make_float2(c[mi][ni][2] + r1.x, c[mi][ni][3] + r1.y);
            }
        }
}

__global__ __launch_bounds__(256) void av_mma(const __nv_bfloat16* __restrict__ attnb,
                                              const __nv_bfloat16* __restrict__ Vb,
                                              __nv_bfloat16* __restrict__ ctxb) {
    const int z = blockIdx.y, b = z >> 3, h = z & 7;
    const int q0 = blockIdx.x * 128;
    mma_gemm_128x64<true>(attnb + (long)z * SS * SS + (long)q0 * SS, SS,
                          Vb + (long)b * SS * DD + h * 64, DD, SS,
                          nullptr, ctxb + (long)b * SS * DD + (long)q0 * DD + h * 64, DD, nullptr);
}

__global__ __launch_bounds__(256) void fc_mma(const __nv_bfloat16* __restrict__ ctxb,
                                              const __nv_bfloat16* __restrict__ wfcb,
                                              const float* __restrict__ res,
                                              float* __restrict__ out) {
    const int bn = blockIdx.x * 64;
    const long bm = (long)blockIdx.y * 128;
    mma_gemm_128x64<false>(ctxb + bm * DD, DD, wfcb + bn, DD, DD,
                           out + bm * DD + bn, nullptr, DD, res + bm * DD + bn);
}

__global__ void cvt_wfc(const float* __restrict__ w, __nv_bfloat16* __restrict__ o) {
    int i = blockIdx.x * 256 + threadIdx.x;
    float2 v = *(const float2*)&w[2 * i];
    *(__nv_bfloat162*)&o[2 * i] = __float22bfloat162_rn(v);
}

// ----------------------------------------------------------------------------
// Row softmax; writes f32 (output) + bf16 copy.
// ----------------------------------------------------------------------------
__global__ void softmax_kernel(float* __restrict__ attn, __nv_bfloat16* __restrict__ attnb) {
    const long row = blockIdx.x;
    float* p = attn + row * SS;
    const int tid = threadIdx.x;
    float4 v = *(const float4*)&p[tid * 4];
    float mx = fmaxf(fmaxf(v.x, v.y), fmaxf(v.z, v.w));
#pragma unroll
    for (int o = 16; o; o >>= 1) mx = fmaxf(mx, __shfl_xor_sync(0xffffffffu, mx, o));
    __shared__ float rmx[8], rsm[8];
    if ((tid & 31) == 0) rmx[tid >> 5] = mx;
    __syncthreads();
    float bm = rmx[0];
#pragma unroll
    for (int w = 1; w < 8; w++) bm = fmaxf(bm, rmx[w]);
    v.x = __expf(v.x - bm); v.y = __expf(v.y - bm);
    v.z = __expf(v.z - bm); v.w = __expf(v.w - bm);
    float s = v.x + v.y + v.z + v.w;
#pragma unroll
    for (int o = 16; o; o >>= 1) s += __shfl_xor_sync(0xffffffffu, s, o);
    if ((tid & 31) == 0) rsm[tid >> 5] = s;
    __syncthreads();
    float tot = 0.f;
#pragma unroll
    for (int w = 0; w < 8; w++) tot += rsm[w];
    float inv = 1.f / tot;
    v.x *= inv; v.y *= inv; v.z *= inv; v.w *= inv;
    *(float4*)&p[tid * 4] = v;
    __nv_bfloat162* pb = (__nv_bfloat162*)(attnb + row * SS);
    pb[tid * 2 + 0] = __float22bfloat162_rn(make_float2(v.x, v.y));
    pb[tid * 2 + 1] = __float22bfloat162_rn(make_float2(v.z, v.w));
}

// ----------------------------------------------------------------------------
// In-place LayerNorm over last dim (512). grid = ROWS, 256 threads.
// ----------------------------------------------------------------------------
__global__ void ln_kernel(float* __restrict__ out, const float* __restrict__ g,
                          const float* __restrict__ bta) {
    const long row = blockIdx.x;
    float* p = out + row * DD;
    const int tid = threadIdx.x;
    float x0 = p[tid], x1 = p[tid + 256];
    float s = x0 + x1, ss = x0 * x0 + x1 * x1;
#pragma unroll
    for (int o = 16; o; o >>= 1) {
        s += __shfl_xor_sync(0xffffffffu, s, o);
        ss += __shfl_xor_sync(0xffffffffu, ss, o);
    }
    __shared__ float rs[8], rss[8];
    if ((tid & 31) == 0) { rs[tid >> 5] = s; rss[tid >> 5] = ss; }
    __syncthreads();
    float S = 0.f, SSq = 0.f;
#pragma unroll
    for (int w = 0; w < 8; w++) { S += rs[w]; SSq += rss[w]; }
    float mu = S * (1.f / 512.f);
    float var = SSq * (1.f / 512.f) - mu * mu;
    float inv = rsqrtf(var + 1e-5f);
    p[tid] = (x0 - mu) * inv * g[tid] + bta[tid];
    p[tid + 256] = (x1 - mu) * inv * g[tid + 256] + bta[tid + 256];
}

// ----------------------------------------------------------------------------
extern "C" void kernel_launch(void* const* d_in, const int* in_sizes, int n_in,
                              void* d_out, int out_size) {
    const float* input_Q = (const float*)d_in[0];
    const float* input_K = (const float*)d_in[1];
    const float* input_V = (const float*)d_in[2];
    const int* attn_if = (const int*)d_in[4];
    const int* itype = (const int*)d_in[5];
    const float* im = (const float*)d_in[6];
    const float* w_q = (const float*)d_in[9];
    const float* w_k = (const float*)d_in[10];
    const float* w_v = (const float*)d_in[11];
    const float* w_fc = (const float*)d_in[12];
    const float* ln_g = (const float*)d_in[13];
    const float* ln_b = (const float*)d_in[14];
    const float* type_emb = (const float*)d_in[15];
    const float* w_feat = (const float*)d_in[16];

    float* out = (float*)d_out;
    float* attn = out + (size_t)ROWS * DD;

    float *Qp, *Kp;
    __nv_bfloat16 *Vpb, *ctxb, *attnb, *wfcb;
    cudaGetSymbolAddress((void**)&Qp, g_Qp);
    cudaGetSymbolAddress((void**)&Kp, g_Kp);
    cudaGetSymbolAddress((void**)&Vpb, g_Vpb);
    cudaGetSymbolAddress((void**)&ctxb, g_ctxb);
    cudaGetSymbolAddress((void**)&attnb, g_attnb);
    cudaGetSymbolAddress((void**)&wfcb, g_wfcb);

    cvt_wfc<<<DD * DD / 512, 256>>>(w_fc, wfcb);

    // Fused projections (tf32 MMA): Q,K fp32 out; V bf16 out
    dim3 gproj(DD / 128, ROWS / 128, 3);
    proj3_kernel<<<gproj, 256>>>(input_Q, input_K, input_V, w_q, w_k, w_v, Qp, Kp, Vpb);

    // Scores + bias (tf32 MMA) -> attn region (raw)
    size_t smem = (size_t)(2 * 64 * 68) * sizeof(uint32_t) + (size_t)8 * 64 * 64 * sizeof(__nv_bfloat16);
    cudaFuncSetAttribute(scores_kernel, cudaFuncAttributeMaxDynamicSharedMemorySize, (int)smem);
    dim3 gsc(SS / 64, SS / 64, BB);
    scores_kernel<<<gsc, 256, smem>>>(Qp, Kp, attn_if, itype, im, type_emb, w_feat, attn);

    // Softmax in place + bf16 copy
    softmax_kernel<<<BB * HH * SS, 256>>>(attn, attnb);

    // attn @ V -> ctx (bf16 MMA)
    dim3 gav(SS / 128, BB * HH);
    av_mma<<<gav, 256>>>(attnb, Vpb, ctxb);

    // FC + residual -> out (bf16 MMA)
    dim3 gfc(DD / 64, ROWS / 128);
    fc_mma<<<gfc, 256>>>(ctxb, wfcb, input_Q, out);

    // LayerNorm in place
    ln_kernel<<<ROWS, 256>>>(out, ln_g, ln_b);
}

// round 8
// speedup vs baseline: 2.2519x; 1.0700x over previous
#include <cuda_runtime.h>
#include <cuda_bf16.h>
#include <math.h>
#include <stdint.h>

// Problem constants
#define BB 4
#define SS 1024
#define DD 512
#define HH 8
#define ROWS (BB*SS)          // 4096
#define NEGV (-1e9f)

// Scratch (device globals; no allocation allowed)
__device__ float g_Qp[ROWS*DD];
__device__ float g_Kp[ROWS*DD];
__device__ __nv_bfloat16 g_Vpb[ROWS*DD];
__device__ __nv_bfloat16 g_ctxb[ROWS*DD];
__device__ __nv_bfloat16 g_wfcb[DD*DD];
__device__ float g_partial[BB*HH*SS*16];   // per-row, per-ktile exp sums

// ============================ MMA helpers ===================================
__device__ __forceinline__ uint32_t smem_u32(const void* p) {
    return (uint32_t)__cvta_generic_to_shared(p);
}
__device__ __forceinline__ uint32_t f2tf32(float f) {
    uint32_t r; asm("cvt.rna.tf32.f32 %0, %1;" : "=r"(r) : "f"(f)); return r;
}
__device__ __forceinline__ void mma_tf32(float& c0, float& c1, float& c2, float& c3,
        uint32_t a0, uint32_t a1, uint32_t a2, uint32_t a3, uint32_t b0, uint32_t b1) {
    asm volatile("mma.sync.aligned.m16n8k8.row.col.f32.tf32.tf32.f32 "
        "{%0,%1,%2,%3}, {%4,%5,%6,%7}, {%8,%9}, {%0,%1,%2,%3};\n"
        : "+f"(c0), "+f"(c1), "+f"(c2), "+f"(c3)
        : "r"(a0), "r"(a1), "r"(a2), "r"(a3), "r"(b0), "r"(b1));
}
__device__ __forceinline__ void ldsm_x4(uint32_t& r0, uint32_t& r1, uint32_t& r2, uint32_t& r3, uint32_t addr) {
    asm volatile("ldmatrix.sync.aligned.m8n8.x4.shared.b16 {%0,%1,%2,%3}, [%4];\n"
        : "=r"(r0), "=r"(r1), "=r"(r2), "=r"(r3) : "r"(addr));
}
__device__ __forceinline__ void ldsm_x4_t(uint32_t& r0, uint32_t& r1, uint32_t& r2, uint32_t& r3, uint32_t addr) {
    asm volatile("ldmatrix.sync.aligned.m8n8.x4.trans.shared.b16 {%0,%1,%2,%3}, [%4];\n"
        : "=r"(r0), "=r"(r1), "=r"(r2), "=r"(r3) : "r"(addr));
}
__device__ __forceinline__ void mma_bf16(float& c0, float& c1, float& c2, float& c3,
        uint32_t a0, uint32_t a1, uint32_t a2, uint32_t a3, uint32_t b0, uint32_t b1) {
    asm volatile("mma.sync.aligned.m16n8k16.row.col.f32.bf16.bf16.f32 "
        "{%0,%1,%2,%3}, {%4,%5,%6,%7}, {%8,%9}, {%0,%1,%2,%3};\n"
        : "+f"(c0), "+f"(c1), "+f"(c2), "+f"(c3)
        : "r"(a0), "r"(a1), "r"(a2), "r"(a3), "r"(b0), "r"(b1));
}
__device__ __forceinline__ uint32_t bf2x(float a, float b) {
    __nv_bfloat162 h = __float22bfloat162_rn(make_float2(a, b));
    uint32_t u; memcpy(&u, &h, 4); return u;
}

// ----------------------------------------------------------------------------
// tf32 GEMM: C[128,128] = A[.,K]f32 @ B[K,.]f32, BK=16, 256 thr / 8 warps.
// ----------------------------------------------------------------------------
template<bool OUT_BF16>
__device__ __forceinline__ void tf32_gemm_128x128(
        const float* __restrict__ A, const float* __restrict__ B,
        float* __restrict__ Cf, __nv_bfloat16* __restrict__ Cb,
        int K, int lda, int ldb, int ldc, int bm, int bn) {
    __shared__ uint32_t As[128 * 20];
    __shared__ uint32_t Bs[16 * 132];
    const int tid = threadIdx.x;
    const int lane = tid & 31, w = tid >> 5;
    const int wm = w >> 1, wn = w & 1;
    const int g = lane >> 2, t = lane & 3;

    float acc[2][8][4];
#pragma unroll
    for (int mi = 0; mi < 2; mi++)
#pragma unroll
        for (int ni = 0; ni < 8; ni++)
#pragma unroll
            for (int r = 0; r < 4; r++) acc[mi][ni][r] = 0.f;

    const int rA = tid >> 2, fA = tid & 3;
    const int kB = tid >> 5, cB = tid & 31;

    float4 pa0 = *(const float4*)&A[(long)(bm + rA) * lda + 4 * fA];
    float4 pa1 = *(const float4*)&A[(long)(bm + rA + 64) * lda + 4 * fA];
    float4 pb0 = *(const float4*)&B[(long)kB * ldb + bn + 4 * cB];
    float4 pb1 = *(const float4*)&B[(long)(kB + 8) * ldb + bn + 4 * cB];

    for (int k0 = 0; k0 < K; k0 += 16) {
        __syncthreads();
        {
            uint4 v0 = make_uint4(f2tf32(pa0.x), f2tf32(pa0.y), f2tf32(pa0.z), f2tf32(pa0.w));
            uint4 v1 = make_uint4(f2tf32(pa1.x), f2tf32(pa1.y), f2tf32(pa1.z), f2tf32(pa1.w));
            *(uint4*)&As[rA * 20 + 4 * fA] = v0;
            *(uint4*)&As[(rA + 64) * 20 + 4 * fA] = v1;
            uint4 w0 = make_uint4(f2tf32(pb0.x), f2tf32(pb0.y), f2tf32(pb0.z), f2tf32(pb0.w));
            uint4 w1 = make_uint4(f2tf32(pb1.x), f2tf32(pb1.y), f2tf32(pb1.z), f2tf32(pb1.w));
            *(uint4*)&Bs[kB * 132 + 4 * cB] = w0;
            *(uint4*)&Bs[(kB + 8) * 132 + 4 * cB] = w1;
        }
        __syncthreads();
        if (k0 + 16 < K) {
            pa0 = *(const float4*)&A[(long)(bm + rA) * lda + k0 + 16 + 4 * fA];
            pa1 = *(const float4*)&A[(long)(bm + rA + 64) * lda + k0 + 16 + 4 * fA];
            pb0 = *(const float4*)&B[(long)(k0 + 16 + kB) * ldb + bn + 4 * cB];
            pb1 = *(const float4*)&B[(long)(k0 + 24 + kB) * ldb + bn + 4 * cB];
        }
#pragma unroll
        for (int ks = 0; ks < 16; ks += 8) {
            uint32_t a[2][4];
#pragma unroll
            for (int mi = 0; mi < 2; mi++) {
                int rb = (32 * wm + 16 * mi + g) * 20 + ks + t;
                a[mi][0] = As[rb];
                a[mi][1] = As[rb + 8 * 20];
                a[mi][2] = As[rb + 4];
                a[mi][3] = As[rb + 8 * 20 + 4];
            }
            uint32_t bb[8][2];
#pragma unroll
            for (int ni = 0; ni < 8; ni++) {
                int nb = 64 * wn + 8 * ni + g;
                bb[ni][0] = Bs[(ks + t) * 132 + nb];
                bb[ni][1] = Bs[(ks + t + 4) * 132 + nb];
            }
#pragma unroll
            for (int mi = 0; mi < 2; mi++)
#pragma unroll
                for (int ni = 0; ni < 8; ni++)
                    mma_tf32(acc[mi][ni][0], acc[mi][ni][1], acc[mi][ni][2], acc[mi][ni][3],
                             a[mi][0], a[mi][1], a[mi][2], a[mi][3], bb[ni][0], bb[ni][1]);
        }
    }

#pragma unroll
    for (int mi = 0; mi < 2; mi++)
#pragma unroll
        for (int ni = 0; ni < 8; ni++) {
            long r0 = bm + 32 * wm + 16 * mi + g;
            long cc = bn + 64 * wn + 8 * ni + 2 * t;
            if (OUT_BF16) {
                *(__nv_bfloat162*)&Cb[r0 * ldc + cc] =
                    __float22bfloat162_rn(make_float2(acc[mi][ni][0], acc[mi][ni][1]));
                *(__nv_bfloat162*)&Cb[(r0 + 8) * ldc + cc] =
                    __float22bfloat162_rn(make_float2(acc[mi][ni][2], acc[mi][ni][3]));
            } else {
                *(float2*)&Cf[r0 * ldc + cc] = make_float2(acc[mi][ni][0], acc[mi][ni][1]);
                *(float2*)&Cf[(r0 + 8) * ldc + cc] = make_float2(acc[mi][ni][2], acc[mi][ni][3]);
            }
        }
}

// Fused Q/K/V projections; V writes bf16.
__global__ __launch_bounds__(256) void proj3_kernel(
        const float* __restrict__ Aq, const float* __restrict__ Ak, const float* __restrict__ Av,
        const float* __restrict__ Wq, const float* __restrict__ Wk, const float* __restrict__ Wv,
        float* __restrict__ Cq, float* __restrict__ Ck, __nv_bfloat16* __restrict__ Cvb) {
    const int z = blockIdx.z;
    const float* A = (z == 0) ? Aq : (z == 1) ? Ak : Av;
    const float* B = (z == 0) ? Wq : (z == 1) ? Wk : Wv;
    if (z == 2)
        tf32_gemm_128x128<true>(A, B, nullptr, Cvb, DD, DD, DD, DD, blockIdx.y * 128, blockIdx.x * 128);
    else
        tf32_gemm_128x128<false>(A, B, (z == 0) ? Cq : Ck, nullptr, DD, DD, DD, DD, blockIdx.y * 128, blockIdx.x * 128);
}

// ----------------------------------------------------------------------------
// Scores + bias + exp. Block = (k-tile 64, q-tile 64, batch). 256 threads.
// Writes e = exp(score+bias) (unnormalized) to attn region, and per-row
// per-ktile partial sums to g_partial (deterministic, no atomics).
// Next-head Q/K register prefetch hides gmem latency across the head loop.
// ----------------------------------------------------------------------------
__global__ __launch_bounds__(256) void scores_kernel(
        const float* __restrict__ Qp, const float* __restrict__ Kp,
        const int* __restrict__ attn_if, const int* __restrict__ itype,
        const float* __restrict__ im, const float* __restrict__ type_emb,
        const float* __restrict__ w_feat, float* __restrict__ attn_out,
        float* __restrict__ partial) {
    extern __shared__ char smraw[];
    uint32_t* Qt = (uint32_t*)smraw;                 // [64 q][68] tf32
    uint32_t* Kt = Qt + 64 * 68;                     // [64 k][68] tf32
    __nv_bfloat16* biasS = (__nv_bfloat16*)(Kt + 64 * 68);  // 8*64*64

    const int b = blockIdx.z;
    const int q0 = blockIdx.y * 64;
    const int k0 = blockIdx.x * 64;
    const int kt = blockIdx.x;
    const int tid = threadIdx.x;
    const int lane = tid & 31, w = tid >> 5;
    const int wm = w >> 1, wn = w & 1;               // 4x2 warp grid, tile m16 x n32
    const int g = lane >> 2, t = lane & 3;

    __shared__ float wf[6][8];
    __shared__ float smsum[128];                     // [row][wn]
    if (tid < 48) wf[tid / 8][tid % 8] = w_feat[tid];
    __syncthreads();

    // Per-pair bias for all 8 heads (computed once).
#pragma unroll
    for (int l = 0; l < 16; l++) {
        int idx = tid + l * 256;
        int qi = idx >> 6, ki = idx & 63;
        long pair = ((long)(b * SS + q0 + qi)) * SS + (k0 + ki);
        if (attn_if[pair] != 0) {
#pragma unroll
            for (int h = 0; h < 8; h++)
                biasS[h * 4096 + qi * 64 + ki] = __float2bfloat16(NEGV);
        } else {
            int tt = itype[pair];
            const float* e = type_emb + (long)tt * 8;
            const float2* imp = (const float2*)(im + pair * 6);
            float2 p0 = imp[0], p1 = imp[1], p2 = imp[2];
#pragma unroll
            for (int h = 0; h < 8; h++) {
                float s = p0.x * wf[0][h] + p0.y * wf[1][h] + p1.x * wf[2][h]
                        + p1.y * wf[3][h] + p2.x * wf[4][h] + p2.y * wf[5][h];
                s = fmaxf(s, 0.f) + e[h];
                biasS[h * 4096 + qi * 64 + ki] = __float2bfloat16(s);
            }
        }
    }

    const int fL = tid & 15, rL = tid >> 4;

    // Prefetch head 0 Q/K into registers
    float4 q4[4], k4[4];
#pragma unroll
    for (int l = 0; l < 4; l++) {
        int r = rL + l * 16;
        q4[l] = *(const float4*)&Qp[((long)(b * SS + q0 + r)) * DD + 4 * fL];
        k4[l] = *(const float4*)&Kp[((long)(b * SS + k0 + r)) * DD + 4 * fL];
    }

    for (int h = 0; h < 8; h++) {
        __syncthreads();
        // Stage current head tiles (tf32 rounding)
#pragma unroll
        for (int l = 0; l < 4; l++) {
            int r = rL + l * 16;
            *(uint4*)&Qt[r * 68 + 4 * fL] = make_uint4(f2tf32(q4[l].x), f2tf32(q4[l].y), f2tf32(q4[l].z), f2tf32(q4[l].w));
            *(uint4*)&Kt[r * 68 + 4 * fL] = make_uint4(f2tf32(k4[l].x), f2tf32(k4[l].y), f2tf32(k4[l].z), f2tf32(k4[l].w));
        }
        __syncthreads();
        // Prefetch next head
        if (h + 1 < 8) {
#pragma unroll
            for (int l = 0; l < 4; l++) {
                int r = rL + l * 16;
                q4[l] = *(const float4*)&Qp[((long)(b * SS + q0 + r)) * DD + (h + 1) * 64 + 4 * fL];
                k4[l] = *(const float4*)&Kp[((long)(b * SS + k0 + r)) * DD + (h + 1) * 64 + 4 * fL];
            }
        }

        float acc[4][4];
#pragma unroll
        for (int ni = 0; ni < 4; ni++)
#pragma unroll
            for (int r = 0; r < 4; r++) acc[ni][r] = 0.f;

#pragma unroll
        for (int k8 = 0; k8 < 64; k8 += 8) {
            int rb = (16 * wm + g) * 68 + k8 + t;
            uint32_t a0 = Qt[rb];
            uint32_t a1 = Qt[rb + 8 * 68];
            uint32_t a2 = Qt[rb + 4];
            uint32_t a3 = Qt[rb + 8 * 68 + 4];
#pragma unroll
            for (int ni = 0; ni < 4; ni++) {
                int nb = (32 * wn + 8 * ni + g) * 68 + k8 + t;
                uint32_t b0 = Kt[nb];
                uint32_t b1 = Kt[nb + 4];
                mma_tf32(acc[ni][0], acc[ni][1], acc[ni][2], acc[ni][3], a0, a1, a2, a3, b0, b1);
            }
        }

        // Epilogue: e = exp(score + bias), write + row partial sums
        float* outp = attn_out + (((long)(b * HH + h) * SS + q0)) * SS + k0;
        const int row0 = 16 * wm + g;
        float sum0 = 0.f, sum1 = 0.f;
#pragma unroll
        for (int ni = 0; ni < 4; ni++) {
            int col = 32 * wn + 8 * ni + 2 * t;
            __nv_bfloat162 bA = *(const __nv_bfloat162*)&biasS[h * 4096 + row0 * 64 + col];
            __nv_bfloat162 bB = *(const __nv_bfloat162*)&biasS[h * 4096 + (row0 + 8) * 64 + col];
            float e0 = __expf(acc[ni][0] * 0.125f + __bfloat162float(bA.x));
            float e1 = __expf(acc[ni][1] * 0.125f + __bfloat162float(bA.y));
            float e2 = __expf(acc[ni][2] * 0.125f + __bfloat162float(bB.x));
            float e3 = __expf(acc[ni][3] * 0.125f + __bfloat162float(bB.y));
            *(float2*)&outp[(long)row0 * SS + col] = make_float2(e0, e1);
            *(float2*)&outp[(long)(row0 + 8) * SS + col] = make_float2(e2, e3);
            sum0 += e0 + e1;
            sum1 += e2 + e3;
        }
        // Reduce over t (groups of 4 lanes share a row)
        sum0 += __shfl_xor_sync(0xffffffffu, sum0, 1);
        sum0 += __shfl_xor_sync(0xffffffffu, sum0, 2);
        sum1 += __shfl_xor_sync(0xffffffffu, sum1, 1);
        sum1 += __shfl_xor_sync(0xffffffffu, sum1, 2);
        if (t == 0) {
            smsum[row0 * 2 + wn] = sum0;
            smsum[(row0 + 8) * 2 + wn] = sum1;
        }
        __syncthreads();
        if (tid < 64)
            partial[((long)(b * HH + h) * SS + q0 + tid) * 16 + kt] = smsum[tid * 2] + smsum[tid * 2 + 1];
    }
}

// ----------------------------------------------------------------------------
// av: ctx = softmax(attn) @ V. Reads raw e (f32), normalizes by row sums
// (from partial), writes normalized attn f32 IN PLACE, converts to bf16
// fragments, bf16 MMA with V. grid (S/128, B*H).
// ----------------------------------------------------------------------------
__global__ __launch_bounds__(256) void av_mma(float* attn,
                                              const __nv_bfloat16* __restrict__ Vb,
                                              const float* __restrict__ partial,
                                              __nv_bfloat16* __restrict__ ctxb) {
    __shared__ __nv_bfloat16 As[128 * 40];
    __shared__ __nv_bfloat16 Bs[32 * 72];
    __shared__ float invs[128];
    const int z = blockIdx.y, b = z >> 3, h = z & 7;
    const int q0 = blockIdx.x * 128;
    float* A = attn + (long)z * SS * SS + (long)q0 * SS;
    const __nv_bfloat16* Bv = Vb + (long)b * SS * DD + h * 64;
    const int tid = threadIdx.x;
    const int lane = tid & 31, w = tid >> 5;
    const int wm = w >> 1, wn = w & 1;

    // Deterministic row sums: fixed-order sum of 16 partials per row.
    if (tid < 128) {
        const float* pp = partial + ((long)z * SS + q0 + tid) * 16;
        float s = 0.f;
#pragma unroll
        for (int i = 0; i < 16; i++) s += pp[i];
        invs[tid] = 1.f / s;
    }
    __syncthreads();

    float c[2][4][4];
#pragma unroll
    for (int mi = 0; mi < 2; mi++)
#pragma unroll
        for (int ni = 0; ni < 4; ni++)
#pragma unroll
            for (int r = 0; r < 4; r++) c[mi][ni][r] = 0.f;

    const int arow = tid >> 2, aq = tid & 3;      // A: rows {arow, arow+64}, cols 8aq..8aq+7
    const int brow = tid >> 3, bseg = tid & 7;

    const float ia0 = invs[arow], ia1 = invs[arow + 64];

    float4 pa00 = *(const float4*)&A[(long)arow * SS + 8 * aq];
    float4 pa01 = *(const float4*)&A[(long)arow * SS + 8 * aq + 4];
    float4 pa10 = *(const float4*)&A[(long)(arow + 64) * SS + 8 * aq];
    float4 pa11 = *(const float4*)&A[(long)(arow + 64) * SS + 8 * aq + 4];
    uint4 pb  = *(const uint4*)&Bv[(long)brow * DD + 8 * bseg];

    for (int k0 = 0; k0 < SS; k0 += 32) {
        __syncthreads();
        {
            float4 u0 = make_float4(pa00.x * ia0, pa00.y * ia0, pa00.z * ia0, pa00.w * ia0);
            float4 u1 = make_float4(pa01.x * ia0, pa01.y * ia0, pa01.z * ia0, pa01.w * ia0);
            float4 v0 = make_float4(pa10.x * ia1, pa10.y * ia1, pa10.z * ia1, pa10.w * ia1);
            float4 v1 = make_float4(pa11.x * ia1, pa11.y * ia1, pa11.z * ia1, pa11.w * ia1);
            // Write normalized attn (final output) in place
            *(float4*)&A[(long)arow * SS + k0 + 8 * aq] = u0;
            *(float4*)&A[(long)arow * SS + k0 + 8 * aq + 4] = u1;
            *(float4*)&A[(long)(arow + 64) * SS + k0 + 8 * aq] = v0;
            *(float4*)&A[(long)(arow + 64) * SS + k0 + 8 * aq + 4] = v1;
            // bf16 fragments to smem
            uint4 pk0 = make_uint4(bf2x(u0.x, u0.y), bf2x(u0.z, u0.w), bf2x(u1.x, u1.y), bf2x(u1.z, u1.w));
            uint4 pk1 = make_uint4(bf2x(v0.x, v0.y), bf2x(v0.z, v0.w), bf2x(v1.x, v1.y), bf2x(v1.z, v1.w));
            *(uint4*)&As[arow * 40 + 8 * aq] = pk0;
            *(uint4*)&As[(arow + 64) * 40 + 8 * aq] = pk1;
            *(uint4*)&Bs[brow * 72 + 8 * bseg] = pb;
        }
        __syncthreads();
        if (k0 + 32 < SS) {
            pa00 = *(const float4*)&A[(long)arow * SS + k0 + 32 + 8 * aq];
            pa01 = *(const float4*)&A[(long)arow * SS + k0 + 32 + 8 * aq + 4];
            pa10 = *(const float4*)&A[(long)(arow + 64) * SS + k0 + 32 + 8 * aq];
            pa11 = *(const float4*)&A[(long)(arow + 64) * SS + k0 + 32 + 8 * aq + 4];
            pb  = *(const uint4*)&Bv[(long)(k0 + 32 + brow) * DD + 8 * bseg];
        }
#pragma unroll
        for (int kk = 0; kk < 32; kk += 16) {
            uint32_t a[2][4];
#pragma unroll
            for (int mi = 0; mi < 2; mi++) {
                uint32_t addr = smem_u32(&As[(32 * wm + 16 * mi + (lane & 15)) * 40 + kk + ((lane >> 4) << 3)]);
                ldsm_x4(a[mi][0], a[mi][1], a[mi][2], a[mi][3], addr);
            }
            uint32_t bf[2][4];
#pragma unroll
            for (int nb = 0; nb < 2; nb++) {
                uint32_t addr = smem_u32(&Bs[(kk + (lane & 15)) * 72 + 32 * wn + 16 * nb + ((lane >> 4) << 3)]);
                ldsm_x4_t(bf[nb][0], bf[nb][1], bf[nb][2], bf[nb][3], addr);
            }
#pragma unroll
            for (int mi = 0; mi < 2; mi++)
#pragma unroll
                for (int ni = 0; ni < 4; ni++) {
                    int nb = ni >> 1, h2 = (ni & 1) * 2;
                    mma_bf16(c[mi][ni][0], c[mi][ni][1], c[mi][ni][2], c[mi][ni][3],
                             a[mi][0], a[mi][1], a[mi][2], a[mi][3], bf[nb][h2], bf[nb][h2 + 1]);
                }
        }
    }

    __nv_bfloat16* C = ctxb + (long)b * SS * DD + (long)q0 * DD + h * 64;
#pragma unroll
    for (int mi = 0; mi < 2; mi++)
#pragma unroll
        for (int ni = 0; ni < 4; ni++) {
            int r = 32 * wm + 16 * mi + (lane >> 2);
            int cc = 32 * wn + 8 * ni + (lane & 3) * 2;
            *(__nv_bfloat162*)&C[(long)r * DD + cc] =
                __float22bfloat162_rn(make_float2(c[mi][ni][0], c[mi][ni][1]));
            *(__nv_bfloat162*)&C[(long)(r + 8) * DD + cc] =
                __float22bfloat162_rn(make_float2(c[mi][ni][2], c[mi][ni][3]));
        }
}

// ----------------------------------------------------------------------------
// bf16 GEMM (FC): C[128,64] = A[128,K] @ B[K,64] + Res, f32 out.
// ----------------------------------------------------------------------------
__global__ __launch_bounds__(256) void fc_mma(const __nv_bfloat16* __restrict__ A,
                                              const __nv_bfloat16* __restrict__ wfcb,
                                              const float* __restrict__ res,
                                              float* __restrict__ out) {
    __shared__ __nv_bfloat16 As[128 * 40];
    __shared__ __nv_bfloat16 Bs[32 * 72];
    const int bn = blockIdx.x * 64;
    const long bm = (long)blockIdx.y * 128;
    const __nv_bfloat16* Ab = A + bm * DD;
    const __nv_bfloat16* B = wfcb + bn;
    const float* Res = res + bm * DD + bn;
    float* Cf = out + bm * DD + bn;
    const int tid = threadIdx.x;
    const int lane = tid & 31, w = tid >> 5;
    const int wm = w >> 1, wn = w & 1;

    float c[2][4][4];
#pragma unroll
    for (int mi = 0; mi < 2; mi++)
#pragma unroll
        for (int ni = 0; ni < 4; ni++)
#pragma unroll
            for (int r = 0; r < 4; r++) c[mi][ni][r] = 0.f;

    const int arow = tid >> 2, aq = tid & 3;
    const int brow = tid >> 3, bseg = tid & 7;

    uint4 pa0 = *(const uint4*)&Ab[(long)arow * DD + 8 * aq];
    uint4 pa1 = *(const uint4*)&Ab[(long)(arow + 64) * DD + 8 * aq];
    uint4 pb  = *(const uint4*)&B[(long)brow * DD + 8 * bseg];

    for (int k0 = 0; k0 < DD; k0 += 32) {
        __syncthreads();
        *(uint4*)&As[arow * 40 + 8 * aq] = pa0;
        *(uint4*)&As[(arow + 64) * 40 + 8 * aq] = pa1;
        *(uint4*)&Bs[brow * 72 + 8 * bseg] = pb;
        __syncthreads();
        if (k0 + 32 < DD) {
            pa0 = *(const uint4*)&Ab[(long)arow * DD + k0 + 32 + 8 * aq];
            pa1 = *(const uint4*)&Ab[(long)(arow + 64) * DD + k0 + 32 + 8 * aq];
            pb  = *(const uint4*)&B[(long)(k0 + 32 + brow) * DD + 8 * bseg];
        }
#pragma unroll
        for (int kk = 0; kk < 32; kk += 16) {
            uint32_t a[2][4];
#pragma unroll
            for (int mi = 0; mi < 2; mi++) {
                uint32_t addr = smem_u32(&As[(32 * wm + 16 * mi + (lane & 15)) * 40 + kk + ((lane >> 4) << 3)]);
                ldsm_x4(a[mi][0], a[mi][1], a[mi][2], a[mi][3], addr);
            }
            uint32_t bf[2][4];
#pragma unroll
            for (int nb = 0; nb < 2; nb++) {
                uint32_t addr = smem_u32(&Bs[(kk + (lane & 15)) * 72 + 32 * wn + 16 * nb + ((lane >> 4) << 3)]);
                ldsm_x4_t(bf[nb][0], bf[nb][1], bf[nb][2], bf[nb][3], addr);
            }
#pragma unroll
            for (int mi = 0; mi < 2; mi++)
#pragma unroll
                for (int ni = 0; ni < 4; ni++) {
                    int nb = ni >> 1, h2 = (ni & 1) * 2;
                    mma_bf16(c[mi][ni][0], c[mi][ni][1], c[mi][ni][2], c[mi][ni][3],
                             a[mi][0], a[mi][1], a[mi][2], a[mi][3], bf[nb][h2], bf[nb][h2 + 1]);
                }
        }
    }

#pragma unroll
    for (int mi = 0; mi < 2; mi++)
#pragma unroll
        for (int ni = 0; ni < 4; ni++) {
            int r = 32 * wm + 16 * mi + (lane >> 2);
            int cc = 32 * wn + 8 * ni + (lane & 3) * 2;
            float2 r0 = *(const float2*)&Res[(long)r * DD + cc];
            float2 r1 = *(const float2*)&Res[(long)(r + 8) * DD + cc];
            *(float2*)&Cf[(long)r * DD + cc] = make_float2(c[mi][ni][0] + r0.x, c[mi][ni][1] + r0.y);
            *(float2*)&Cf[(long)(r + 8) * DD + cc] = make_float2(c[mi][ni][2] + r1.x, c[mi][ni][3] + r1.y);
        }
}

__global__ void cvt_wfc(const float* __restrict__ w, __nv_bfloat16* __restrict__ o) {
    int i = blockIdx.x * 256 + threadIdx.x;
    float2 v = *(const float2*)&w[2 * i];
    *(__nv_bfloat162*)&o[2 * i] = __float22bfloat162_rn(v);
}

// ----------------------------------------------------------------------------
// In-place LayerNorm over last dim (512). grid = ROWS, 256 threads.
// ----------------------------------------------------------------------------
__global__ void ln_kernel(float* __restrict__ out, const float* __restrict__ g,
                          const float* __restrict__ bta) {
    const long row = blockIdx.x;
    float* p = out + row * DD;
    const int tid = threadIdx.x;
    float x0 = p[tid], x1 = p[tid + 256];
    float s = x0 + x1, ss = x0 * x0 + x1 * x1;
#pragma unroll
    for (int o = 16; o; o >>= 1) {
        s += __shfl_xor_sync(0xffffffffu, s, o);
        ss += __shfl_xor_sync(0xffffffffu, ss, o);
    }
    __shared__ float rs[8], rss[8];
    if ((tid & 31) == 0) { rs[tid >> 5] = s; rss[tid >> 5] = ss; }
    __syncthreads();
    float S = 0.f, SSq = 0.f;
#pragma unroll
    for (int w = 0; w < 8; w++) { S += rs[w]; SSq += rss[w]; }
    float mu = S * (1.f / 512.f);
    float var = SSq * (1.f / 512.f) - mu * mu;
    float inv = rsqrtf(var + 1e-5f);
    p[tid] = (x0 - mu) * inv * g[tid] + bta[tid];
    p[tid + 256] = (x1 - mu) * inv * g[tid + 256] + bta[tid + 256];
}

// ----------------------------------------------------------------------------
extern "C" void kernel_launch(void* const* d_in, const int* in_sizes, int n_in,
                              void* d_out, int out_size) {
    const float* input_Q = (const float*)d_in[0];
    const float* input_K = (const float*)d_in[1];
    const float* input_V = (const float*)d_in[2];
    const int* attn_if = (const int*)d_in[4];
    const int* itype = (const int*)d_in[5];
    const float* im = (const float*)d_in[6];
    const float* w_q = (const float*)d_in[9];
    const float* w_k = (const float*)d_in[10];
    const float* w_v = (const float*)d_in[11];
    const float* w_fc = (const float*)d_in[12];
    const float* ln_g = (const float*)d_in[13];
    const float* ln_b = (const float*)d_in[14];
    const float* type_emb = (const float*)d_in[15];
    const float* w_feat = (const float*)d_in[16];

    float* out = (float*)d_out;
    float* attn = out + (size_t)ROWS * DD;

    float *Qp, *Kp, *partial;
    __nv_bfloat16 *Vpb, *ctxb, *wfcb;
    cudaGetSymbolAddress((void**)&Qp, g_Qp);
    cudaGetSymbolAddress((void**)&Kp, g_Kp);
    cudaGetSymbolAddress((void**)&Vpb, g_Vpb);
    cudaGetSymbolAddress((void**)&ctxb, g_ctxb);
    cudaGetSymbolAddress((void**)&wfcb, g_wfcb);
    cudaGetSymbolAddress((void**)&partial, g_partial);

    cvt_wfc<<<DD * DD / 512, 256>>>(w_fc, wfcb);

    // Fused projections (tf32 MMA): Q,K fp32 out; V bf16 out
    dim3 gproj(DD / 128, ROWS / 128, 3);
    proj3_kernel<<<gproj, 256>>>(input_Q, input_K, input_V, w_q, w_k, w_v, Qp, Kp, Vpb);

    // Scores + bias + exp -> attn region (unnormalized e) + row partial sums
    size_t smem = (size_t)(2 * 64 * 68) * sizeof(uint32_t) + (size_t)8 * 64 * 64 * sizeof(__nv_bfloat16);
    cudaFuncSetAttribute(scores_kernel, cudaFuncAttributeMaxDynamicSharedMemorySize, (int)smem);
    dim3 gsc(SS / 64, SS / 64, BB);
    scores_kernel<<<gsc, 256, smem>>>(Qp, Kp, attn_if, itype, im, type_emb, w_feat, attn, partial);

    // av: normalize (in place) + attn @ V -> ctx (bf16 MMA)
    dim3 gav(SS / 128, BB * HH);
    av_mma<<<gav, 256>>>(attn, Vpb, partial, ctxb);

    // FC + residual -> out (bf16 MMA)
    dim3 gfc(DD / 64, ROWS / 128);
    fc_mma<<<gfc, 256>>>(ctxb, wfcb, input_Q, out);

    // LayerNorm in place
    ln_kernel<<<ROWS, 256>>>(out, ln_g, ln_b);
}

// round 11
// speedup vs baseline: 2.2641x; 1.0054x over previous
#include <cuda_runtime.h>
#include <cuda_bf16.h>
#include <math.h>
#include <stdint.h>

// Problem constants
#define BB 4
#define SS 1024
#define DD 512
#define HH 8
#define ROWS (BB*SS)          // 4096
#define NEGV (-1e9f)

// Scratch (device globals; no allocation allowed)
__device__ float g_Qp[ROWS*DD];
__device__ float g_Kp[ROWS*DD];
__device__ __nv_bfloat16 g_Vpb[ROWS*DD];
__device__ __nv_bfloat16 g_ctxb[ROWS*DD];
__device__ __nv_bfloat16 g_wfcb[DD*DD];
__device__ float g_partial[BB*HH*SS*16];   // per-row, per-ktile exp sums

// ============================ MMA helpers ===================================
__device__ __forceinline__ uint32_t smem_u32(const void* p) {
    return (uint32_t)__cvta_generic_to_shared(p);
}
__device__ __forceinline__ uint32_t f2tf32(float f) {
    uint32_t r; asm("cvt.rna.tf32.f32 %0, %1;" : "=r"(r) : "f"(f)); return r;
}
__device__ __forceinline__ void mma_tf32(float& c0, float& c1, float& c2, float& c3,
        uint32_t a0, uint32_t a1, uint32_t a2, uint32_t a3, uint32_t b0, uint32_t b1) {
    asm volatile("mma.sync.aligned.m16n8k8.row.col.f32.tf32.tf32.f32 "
        "{%0,%1,%2,%3}, {%4,%5,%6,%7}, {%8,%9}, {%0,%1,%2,%3};\n"
        : "+f"(c0), "+f"(c1), "+f"(c2), "+f"(c3)
        : "r"(a0), "r"(a1), "r"(a2), "r"(a3), "r"(b0), "r"(b1));
}
__device__ __forceinline__ void ldsm_x4(uint32_t& r0, uint32_t& r1, uint32_t& r2, uint32_t& r3, uint32_t addr) {
    asm volatile("ldmatrix.sync.aligned.m8n8.x4.shared.b16 {%0,%1,%2,%3}, [%4];\n"
        : "=r"(r0), "=r"(r1), "=r"(r2), "=r"(r3) : "r"(addr));
}
__device__ __forceinline__ void ldsm_x4_t(uint32_t& r0, uint32_t& r1, uint32_t& r2, uint32_t& r3, uint32_t addr) {
    asm volatile("ldmatrix.sync.aligned.m8n8.x4.trans.shared.b16 {%0,%1,%2,%3}, [%4];\n"
        : "=r"(r0), "=r"(r1), "=r"(r2), "=r"(r3) : "r"(addr));
}
__device__ __forceinline__ void mma_bf16(float& c0, float& c1, float& c2, float& c3,
        uint32_t a0, uint32_t a1, uint32_t a2, uint32_t a3, uint32_t b0, uint32_t b1) {
    asm volatile("mma.sync.aligned.m16n8k16.row.col.f32.bf16.bf16.f32 "
        "{%0,%1,%2,%3}, {%4,%5,%6,%7}, {%8,%9}, {%0,%1,%2,%3};\n"
        : "+f"(c0), "+f"(c1), "+f"(c2), "+f"(c3)
        : "r"(a0), "r"(a1), "r"(a2), "r"(a3), "r"(b0), "r"(b1));
}
__device__ __forceinline__ uint32_t bf2x(float a, float b) {
    __nv_bfloat162 h = __float22bfloat162_rn(make_float2(a, b));
    uint32_t u; memcpy(&u, &h, 4); return u;
}

// ----------------------------------------------------------------------------
// tf32 GEMM: C[128,128] = A[.,K]f32 @ B[K,.]f32, BK=16, 256 thr / 8 warps.
// ----------------------------------------------------------------------------
template<bool OUT_BF16>
__device__ __forceinline__ void tf32_gemm_128x128(
        const float* __restrict__ A, const float* __restrict__ B,
        float* __restrict__ Cf, __nv_bfloat16* __restrict__ Cb,
        int K, int lda, int ldb, int ldc, int bm, int bn) {
    __shared__ uint32_t As[128 * 20];
    __shared__ uint32_t Bs[16 * 132];
    const int tid = threadIdx.x;
    const int lane = tid & 31, w = tid >> 5;
    const int wm = w >> 1, wn = w & 1;
    const int g = lane >> 2, t = lane & 3;

    float acc[2][8][4];
#pragma unroll
    for (int mi = 0; mi < 2; mi++)
#pragma unroll
        for (int ni = 0; ni < 8; ni++)
#pragma unroll
            for (int r = 0; r < 4; r++) acc[mi][ni][r] = 0.f;

    const int rA = tid >> 2, fA = tid & 3;
    const int kB = tid >> 5, cB = tid & 31;

    float4 pa0 = *(const float4*)&A[(long)(bm + rA) * lda + 4 * fA];
    float4 pa1 = *(const float4*)&A[(long)(bm + rA + 64) * lda + 4 * fA];
    float4 pb0 = *(const float4*)&B[(long)kB * ldb + bn + 4 * cB];
    float4 pb1 = *(const float4*)&B[(long)(kB + 8) * ldb + bn + 4 * cB];

    for (int k0 = 0; k0 < K; k0 += 16) {
        __syncthreads();
        {
            uint4 v0 = make_uint4(f2tf32(pa0.x), f2tf32(pa0.y), f2tf32(pa0.z), f2tf32(pa0.w));
            uint4 v1 = make_uint4(f2tf32(pa1.x), f2tf32(pa1.y), f2tf32(pa1.z), f2tf32(pa1.w));
            *(uint4*)&As[rA * 20 + 4 * fA] = v0;
            *(uint4*)&As[(rA + 64) * 20 + 4 * fA] = v1;
            uint4 w0 = make_uint4(f2tf32(pb0.x), f2tf32(pb0.y), f2tf32(pb0.z), f2tf32(pb0.w));
            uint4 w1 = make_uint4(f2tf32(pb1.x), f2tf32(pb1.y), f2tf32(pb1.z), f2tf32(pb1.w));
            *(uint4*)&Bs[kB * 132 + 4 * cB] = w0;
            *(uint4*)&Bs[(kB + 8) * 132 + 4 * cB] = w1;
        }
        __syncthreads();
        if (k0 + 16 < K) {
            pa0 = *(const float4*)&A[(long)(bm + rA) * lda + k0 + 16 + 4 * fA];
            pa1 = *(const float4*)&A[(long)(bm + rA + 64) * lda + k0 + 16 + 4 * fA];
            pb0 = *(const float4*)&B[(long)(k0 + 16 + kB) * ldb + bn + 4 * cB];
            pb1 = *(const float4*)&B[(long)(k0 + 24 + kB) * ldb + bn + 4 * cB];
        }
#pragma unroll
        for (int ks = 0; ks < 16; ks += 8) {
            uint32_t a[2][4];
#pragma unroll
            for (int mi = 0; mi < 2; mi++) {
                int rb = (32 * wm + 16 * mi + g) * 20 + ks + t;
                a[mi][0] = As[rb];
                a[mi][1] = As[rb + 8 * 20];
                a[mi][2] = As[rb + 4];
                a[mi][3] = As[rb + 8 * 20 + 4];
            }
            uint32_t bb[8][2];
#pragma unroll
            for (int ni = 0; ni < 8; ni++) {
                int nb = 64 * wn + 8 * ni + g;
                bb[ni][0] = Bs[(ks + t) * 132 + nb];
                bb[ni][1] = Bs[(ks + t + 4) * 132 + nb];
            }
#pragma unroll
            for (int mi = 0; mi < 2; mi++)
#pragma unroll
                for (int ni = 0; ni < 8; ni++)
                    mma_tf32(acc[mi][ni][0], acc[mi][ni][1], acc[mi][ni][2], acc[mi][ni][3],
                             a[mi][0], a[mi][1], a[mi][2], a[mi][3], bb[ni][0], bb[ni][1]);
        }
    }

#pragma unroll
    for (int mi = 0; mi < 2; mi++)
#pragma unroll
        for (int ni = 0; ni < 8; ni++) {
            long r0 = bm + 32 * wm + 16 * mi + g;
            long cc = bn + 64 * wn + 8 * ni + 2 * t;
            if (OUT_BF16) {
                *(__nv_bfloat162*)&Cb[r0 * ldc + cc] =
                    __float22bfloat162_rn(make_float2(acc[mi][ni][0], acc[mi][ni][1]));
                *(__nv_bfloat162*)&Cb[(r0 + 8) * ldc + cc] =
                    __float22bfloat162_rn(make_float2(acc[mi][ni][2], acc[mi][ni][3]));
            } else {
                *(float2*)&Cf[r0 * ldc + cc] = make_float2(acc[mi][ni][0], acc[mi][ni][1]);
                *(float2*)&Cf[(r0 + 8) * ldc + cc] = make_float2(acc[mi][ni][2], acc[mi][ni][3]);
            }
        }
}

// Fused Q/K/V projections; V writes bf16.
__global__ __launch_bounds__(256) void proj3_kernel(
        const float* __restrict__ Aq, const float* __restrict__ Ak, const float* __restrict__ Av,
        const float* __restrict__ Wq, const float* __restrict__ Wk, const float* __restrict__ Wv,
        float* __restrict__ Cq, float* __restrict__ Ck, __nv_bfloat16* __restrict__ Cvb) {
    const int z = blockIdx.z;
    const float* A = (z == 0) ? Aq : (z == 1) ? Ak : Av;
    const float* B = (z == 0) ? Wq : (z == 1) ? Wk : Wv;
    if (z == 2)
        tf32_gemm_128x128<true>(A, B, nullptr, Cvb, DD, DD, DD, DD, blockIdx.y * 128, blockIdx.x * 128);
    else
        tf32_gemm_128x128<false>(A, B, (z == 0) ? Cq : Ck, nullptr, DD, DD, DD, DD, blockIdx.y * 128, blockIdx.x * 128);
}

// ----------------------------------------------------------------------------
// Scores + bias + exp. Block = (k-tile 64, q-tile 64, batch). 256 threads.
// Writes e = exp(score+bias) (unnormalized) to attn region, and per-row
// per-ktile partial sums to g_partial (deterministic, no atomics).
// ----------------------------------------------------------------------------
__global__ __launch_bounds__(256) void scores_kernel(
        const float* __restrict__ Qp, const float* __restrict__ Kp,
        const int* __restrict__ attn_if, const int* __restrict__ itype,
        const float* __restrict__ im, const float* __restrict__ type_emb,
        const float* __restrict__ w_feat, float* __restrict__ attn_out,
        float* __restrict__ partial) {
    extern __shared__ char smraw[];
    uint32_t* Qt = (uint32_t*)smraw;                 // [64 q][68] tf32
    uint32_t* Kt = Qt + 64 * 68;                     // [64 k][68] tf32
    __nv_bfloat16* biasS = (__nv_bfloat16*)(Kt + 64 * 68);  // 8*64*64

    const int b = blockIdx.z;
    const int q0 = blockIdx.y * 64;
    const int k0 = blockIdx.x * 64;
    const int kt = blockIdx.x;
    const int tid = threadIdx.x;
    const int lane = tid & 31, w = tid >> 5;
    const int wm = w >> 1, wn = w & 1;               // 4x2 warp grid, tile m16 x n32
    const int g = lane >> 2, t = lane & 3;

    __shared__ float wf[6][8];
    __shared__ float smsum[128];                     // [row][wn]
    if (tid < 48) wf[tid / 8][tid % 8] = w_feat[tid];
    __syncthreads();

    // Per-pair bias for all 8 heads (computed once).
#pragma unroll
    for (int l = 0; l < 16; l++) {
        int idx = tid + l * 256;
        int qi = idx >> 6, ki = idx & 63;
        long pair = ((long)(b * SS + q0 + qi)) * SS + (k0 + ki);
        if (attn_if[pair] != 0) {
#pragma unroll
            for (int h = 0; h < 8; h++)
                biasS[h * 4096 + qi * 64 + ki] = __float2bfloat16(NEGV);
        } else {
            int tt = itype[pair];
            const float* e = type_emb + (long)tt * 8;
            const float2* imp = (const float2*)(im + pair * 6);
            float2 p0 = imp[0], p1 = imp[1], p2 = imp[2];
#pragma unroll
            for (int h = 0; h < 8; h++) {
                float s = p0.x * wf[0][h] + p0.y * wf[1][h] + p1.x * wf[2][h]
                        + p1.y * wf[3][h] + p2.x * wf[4][h] + p2.y * wf[5][h];
                s = fmaxf(s, 0.f) + e[h];
                biasS[h * 4096 + qi * 64 + ki] = __float2bfloat16(s);
            }
        }
    }

    const int fL = tid & 15, rL = tid >> 4;

    // Prefetch head 0 Q/K into registers
    float4 q4[4], k4[4];
#pragma unroll
    for (int l = 0; l < 4; l++) {
        int r = rL + l * 16;
        q4[l] = *(const float4*)&Qp[((long)(b * SS + q0 + r)) * DD + 4 * fL];
        k4[l] = *(const float4*)&Kp[((long)(b * SS + k0 + r)) * DD + 4 * fL];
    }

    for (int h = 0; h < 8; h++) {
        __syncthreads();
        // Stage current head tiles (tf32 rounding)
#pragma unroll
        for (int l = 0; l < 4; l++) {
            int r = rL + l * 16;
            *(uint4*)&Qt[r * 68 + 4 * fL] = make_uint4(f2tf32(q4[l].x), f2tf32(q4[l].y), f2tf32(q4[l].z), f2tf32(q4[l].w));
            *(uint4*)&Kt[r * 68 + 4 * fL] = make_uint4(f2tf32(k4[l].x), f2tf32(k4[l].y), f2tf32(k4[l].z), f2tf32(k4[l].w));
        }
        __syncthreads();
        // Prefetch next head
        if (h + 1 < 8) {
#pragma unroll
            for (int l = 0; l < 4; l++) {
                int r = rL + l * 16;
                q4[l] = *(const float4*)&Qp[((long)(b * SS + q0 + r)) * DD + (h + 1) * 64 + 4 * fL];
                k4[l] = *(const float4*)&Kp[((long)(b * SS + k0 + r)) * DD + (h + 1) * 64 + 4 * fL];
            }
        }

        float acc[4][4];
#pragma unroll
        for (int ni = 0; ni < 4; ni++)
#pragma unroll
            for (int r = 0; r < 4; r++) acc[ni][r] = 0.f;

#pragma unroll
        for (int k8 = 0; k8 < 64; k8 += 8) {
            int rb = (16 * wm + g) * 68 + k8 + t;
            uint32_t a0 = Qt[rb];
            uint32_t a1 = Qt[rb + 8 * 68];
            uint32_t a2 = Qt[rb + 4];
            uint32_t a3 = Qt[rb + 8 * 68 + 4];
#pragma unroll
            for (int ni = 0; ni < 4; ni++) {
                int nb = (32 * wn + 8 * ni + g) * 68 + k8 + t;
                uint32_t b0 = Kt[nb];
                uint32_t b1 = Kt[nb + 4];
                mma_tf32(acc[ni][0], acc[ni][1], acc[ni][2], acc[ni][3], a0, a1, a2, a3, b0, b1);
            }
        }

        // Epilogue: e = exp(score + bias), write + row partial sums
        float* outp = attn_out + (((long)(b * HH + h) * SS + q0)) * SS + k0;
        const int row0 = 16 * wm + g;
        float sum0 = 0.f, sum1 = 0.f;
#pragma unroll
        for (int ni = 0; ni < 4; ni++) {
            int col = 32 * wn + 8 * ni + 2 * t;
            __nv_bfloat162 bA = *(const __nv_bfloat162*)&biasS[h * 4096 + row0 * 64 + col];
            __nv_bfloat162 bB = *(const __nv_bfloat162*)&biasS[h * 4096 + (row0 + 8) * 64 + col];
            float e0 = __expf(acc[ni][0] * 0.125f + __bfloat162float(bA.x));
            float e1 = __expf(acc[ni][1] * 0.125f + __bfloat162float(bA.y));
            float e2 = __expf(acc[ni][2] * 0.125f + __bfloat162float(bB.x));
            float e3 = __expf(acc[ni][3] * 0.125f + __bfloat162float(bB.y));
            *(float2*)&outp[(long)row0 * SS + col] = make_float2(e0, e1);
            *(float2*)&outp[(long)(row0 + 8) * SS + col] = make_float2(e2, e3);
            sum0 += e0 + e1;
            sum1 += e2 + e3;
        }
        sum0 += __shfl_xor_sync(0xffffffffu, sum0, 1);
        sum0 += __shfl_xor_sync(0xffffffffu, sum0, 2);
        sum1 += __shfl_xor_sync(0xffffffffu, sum1, 1);
        sum1 += __shfl_xor_sync(0xffffffffu, sum1, 2);
        if (t == 0) {
            smsum[row0 * 2 + wn] = sum0;
            smsum[(row0 + 8) * 2 + wn] = sum1;
        }
        __syncthreads();
        if (tid < 64)
            partial[((long)(b * HH + h) * SS + q0 + tid) * 16 + kt] = smsum[tid * 2] + smsum[tid * 2 + 1];
    }
}

// ----------------------------------------------------------------------------
// av: ctx = softmax(attn) @ V. 64-row q-tiles, double-buffered smem,
// gmem prefetch overlapped with MMA. Normalizes raw e by row sums, writes
// normalized attn f32 IN PLACE (final output), bf16 MMA with V.
// grid (S/64, B*H), 256 threads / 8 warps (4x2, warp tile 16x32).
// ----------------------------------------------------------------------------
__global__ __launch_bounds__(256) void av_mma(float* attn,
                                              const __nv_bfloat16* __restrict__ Vb,
                                              const float* __restrict__ partial,
                                              __nv_bfloat16* __restrict__ ctxb) {
    __shared__ __nv_bfloat16 As[2][64 * 40];
    __shared__ __nv_bfloat16 Bs[2][32 * 72];
    __shared__ float invs[64];
    const int z = blockIdx.y, b = z >> 3, h = z & 7;
    const int q0 = blockIdx.x * 64;
    float* A = attn + (long)z * SS * SS + (long)q0 * SS;
    const __nv_bfloat16* Bv = Vb + (long)b * SS * DD + h * 64;
    const int tid = threadIdx.x;
    const int lane = tid & 31, w = tid >> 5;
    const int wm = w >> 1, wn = w & 1;               // 4x2 warps, tile m16 x n32

    // Deterministic row sums: fixed-order sum of 16 partials per row.
    if (tid < 64) {
        const float* pp = partial + ((long)z * SS + q0 + tid) * 16;
        float s = 0.f;
#pragma unroll
        for (int i = 0; i < 16; i++) s += pp[i];
        invs[tid] = 1.f / s;
    }
    __syncthreads();

    float c[4][4];
#pragma unroll
    for (int ni = 0; ni < 4; ni++)
#pragma unroll
        for (int r = 0; r < 4; r++) c[ni][r] = 0.f;

    const int arow = tid >> 2, aq = tid & 3;      // A: row arow, cols 8aq..8aq+7
    const int brow = tid >> 3, bseg = tid & 7;    // B: row brow, cols 8bseg..+7
    const float ia = invs[arow];

    // Stage tile 0
    {
        float4 p0 = *(const float4*)&A[(long)arow * SS + 8 * aq];
        float4 p1 = *(const float4*)&A[(long)arow * SS + 8 * aq + 4];
        uint4 pb = *(const uint4*)&Bv[(long)brow * DD + 8 * bseg];
        float4 u0 = make_float4(p0.x * ia, p0.y * ia, p0.z * ia, p0.w * ia);
        float4 u1 = make_float4(p1.x * ia, p1.y * ia, p1.z * ia, p1.w * ia);
        *(float4*)&A[(long)arow * SS + 8 * aq] = u0;
        *(float4*)&A[(long)arow * SS + 8 * aq + 4] = u1;
        *(uint4*)&As[0][arow * 40 + 8 * aq] =
            make_uint4(bf2x(u0.x, u0.y), bf2x(u0.z, u0.w), bf2x(u1.x, u1.y), bf2x(u1.z, u1.w));
        *(uint4*)&Bs[0][brow * 72 + 8 * bseg] = pb;
    }
    __syncthreads();

    for (int k0 = 0; k0 < SS; k0 += 32) {
        const int cur = (k0 >> 5) & 1;
        const bool more = (k0 + 32 < SS);
        float4 p0, p1; uint4 pb;
        if (more) {
            p0 = *(const float4*)&A[(long)arow * SS + k0 + 32 + 8 * aq];
            p1 = *(const float4*)&A[(long)arow * SS + k0 + 32 + 8 * aq + 4];
            pb = *(const uint4*)&Bv[(long)(k0 + 32 + brow) * DD + 8 * bseg];
        }
        // MMA on buffer cur (overlaps the prefetch above)
#pragma unroll
        for (int kk = 0; kk < 32; kk += 16) {
            uint32_t a[4];
            {
                uint32_t addr = smem_u32(&As[cur][(16 * wm + (lane & 15)) * 40 + kk + ((lane >> 4) << 3)]);
                ldsm_x4(a[0], a[1], a[2], a[3], addr);
            }
            uint32_t bf[2][4];
#pragma unroll
            for (int nb = 0; nb < 2; nb++) {
                uint32_t addr = smem_u32(&Bs[cur][(kk + (lane & 15)) * 72 + 32 * wn + 16 * nb + ((lane >> 4) << 3)]);
                ldsm_x4_t(bf[nb][0], bf[nb][1], bf[nb][2], bf[nb][3], addr);
            }
#pragma unroll
            for (int ni = 0; ni < 4; ni++) {
                int nb = ni >> 1, h2 = (ni & 1) * 2;
                mma_bf16(c[ni][0], c[ni][1], c[ni][2], c[ni][3],
                         a[0], a[1], a[2], a[3], bf[nb][h2], bf[nb][h2 + 1]);
            }
        }
        if (more) {
            float4 u0 = make_float4(p0.x * ia, p0.y * ia, p0.z * ia, p0.w * ia);
            float4 u1 = make_float4(p1.x * ia, p1.y * ia, p1.z * ia, p1.w * ia);
            *(float4*)&A[(long)arow * SS + k0 + 32 + 8 * aq] = u0;
            *(float4*)&A[(long)arow * SS + k0 + 32 + 8 * aq + 4] = u1;
            *(uint4*)&As[1 - cur][arow * 40 + 8 * aq] =
                make_uint4(bf2x(u0.x, u0.y), bf2x(u0.z, u0.w), bf2x(u1.x, u1.y), bf2x(u1.z, u1.w));
            *(uint4*)&Bs[1 - cur][brow * 72 + 8 * bseg] = pb;
        }
        __syncthreads();
    }

    __nv_bfloat16* C = ctxb + (long)b * SS * DD + (long)q0 * DD + h * 64;
#pragma unroll
    for (int ni = 0; ni < 4; ni++) {
        int r = 16 * wm + (lane >> 2);
        int cc = 32 * wn + 8 * ni + (lane & 3) * 2;
        *(__nv_bfloat162*)&C[(long)r * DD + cc] =
            __float22bfloat162_rn(make_float2(c[ni][0], c[ni][1]));
        *(__nv_bfloat162*)&C[(long)(r + 8) * DD + cc] =
            __float22bfloat162_rn(make_float2(c[ni][2], c[ni][3]));
    }
}

// ----------------------------------------------------------------------------
// bf16 GEMM (FC): C[128,64] = A[128,K] @ B[K,64] + Res, f32 out.
// ----------------------------------------------------------------------------
__global__ __launch_bounds__(256) void fc_mma(const __nv_bfloat16* __restrict__ A,
                                              const __nv_bfloat16* __restrict__ wfcb,
                                              const float* __restrict__ res,
                                              float* __restrict__ out) {
    __shared__ __nv_bfloat16 As[128 * 40];
    __shared__ __nv_bfloat16 Bs[32 * 72];
    const int bn = blockIdx.x * 64;
    const long bm = (long)blockIdx.y * 128;
    const __nv_bfloat16* Ab = A + bm * DD;
    const __nv_bfloat16* B = wfcb + bn;
    const float* Res = res + bm * DD + bn;
    float* Cf = out + bm * DD + bn;
    const int tid = threadIdx.x;
    const int lane = tid & 31, w = tid >> 5;
    const int wm = w >> 1, wn = w & 1;

    float c[2][4][4];
#pragma unroll
    for (int mi = 0; mi < 2; mi++)
#pragma unroll
        for (int ni = 0; ni < 4; ni++)
#pragma unroll
            for (int r = 0; r < 4; r++) c[mi][ni][r] = 0.f;

    const int arow = tid >> 2, aq = tid & 3;
    const int brow = tid >> 3, bseg = tid & 7;

    uint4 pa0 = *(const uint4*)&Ab[(long)arow * DD + 8 * aq];
    uint4 pa1 = *(const uint4*)&Ab[(long)(arow + 64) * DD + 8 * aq];
    uint4 pb  = *(const uint4*)&B[(long)brow * DD + 8 * bseg];

    for (int k0 = 0; k0 < DD; k0 += 32) {
        __syncthreads();
        *(uint4*)&As[arow * 40 + 8 * aq] = pa0;
        *(uint4*)&As[(arow + 64) * 40 + 8 * aq] = pa1;
        *(uint4*)&Bs[brow * 72 + 8 * bseg] = pb;
        __syncthreads();
        if (k0 + 32 < DD) {
            pa0 = *(const uint4*)&Ab[(long)arow * DD + k0 + 32 + 8 * aq];
            pa1 = *(const uint4*)&Ab[(long)(arow + 64) * DD + k0 + 32 + 8 * aq];
            pb  = *(const uint4*)&B[(long)(k0 + 32 + brow) * DD + 8 * bseg];
        }
#pragma unroll
        for (int kk = 0; kk < 32; kk += 16) {
            uint32_t a[2][4];
#pragma unroll
            for (int mi = 0; mi < 2; mi++) {
                uint32_t addr = smem_u32(&As[(32 * wm + 16 * mi + (lane & 15)) * 40 + kk + ((lane >> 4) << 3)]);
                ldsm_x4(a[mi][0], a[mi][1], a[mi][2], a[mi][3], addr);
            }
            uint32_t bf[2][4];
#pragma unroll
            for (int nb = 0; nb < 2; nb++) {
                uint32_t addr = smem_u32(&Bs[(kk + (lane & 15)) * 72 + 32 * wn + 16 * nb + ((lane >> 4) << 3)]);
                ldsm_x4_t(bf[nb][0], bf[nb][1], bf[nb][2], bf[nb][3], addr);
            }
#pragma unroll
            for (int mi = 0; mi < 2; mi++)
#pragma unroll
                for (int ni = 0; ni < 4; ni++) {
                    int nb = ni >> 1, h2 = (ni & 1) * 2;
                    mma_bf16(c[mi][ni][0], c[mi][ni][1], c[mi][ni][2], c[mi][ni][3],
                             a[mi][0], a[mi][1], a[mi][2], a[mi][3], bf[nb][h2], bf[nb][h2 + 1]);
                }
        }
    }

#pragma unroll
    for (int mi = 0; mi < 2; mi++)
#pragma unroll
        for (int ni = 0; ni < 4; ni++) {
            int r = 32 * wm + 16 * mi + (lane >> 2);
            int cc = 32 * wn + 8 * ni + (lane & 3) * 2;
            float2 r0 = *(const float2*)&Res[(long)r * DD + cc];
            float2 r1 = *(const float2*)&Res[(long)(r + 8) * DD + cc];
            *(float2*)&Cf[(long)r * DD + cc] = make_float2(c[mi][ni][0] + r0.x, c[mi][ni][1] + r0.y);
            *(float2*)&Cf[(long)(r + 8) * DD + cc] = make_float2(c[mi][ni][2] + r1.x, c[mi][ni][3] + r1.y);
        }
}

__global__ void cvt_wfc(const float* __restrict__ w, __nv_bfloat16* __restrict__ o) {
    int i = blockIdx.x * 256 + threadIdx.x;
    float2 v = *(const float2*)&w[2 * i];
    *(__nv_bfloat162*)&o[2 * i] = __float22bfloat162_rn(v);
}

// ----------------------------------------------------------------------------
// In-place LayerNorm over last dim (512). grid = ROWS, 256 threads.
// ----------------------------------------------------------------------------
__global__ void ln_kernel(float* __restrict__ out, const float* __restrict__ g,
                          const float* __restrict__ bta) {
    const long row = blockIdx.x;
    float* p = out + row * DD;
    const int tid = threadIdx.x;
    float x0 = p[tid], x1 = p[tid + 256];
    float s = x0 + x1, ss = x0 * x0 + x1 * x1;
#pragma unroll
    for (int o = 16; o; o >>= 1) {
        s += __shfl_xor_sync(0xffffffffu, s, o);
        ss += __shfl_xor_sync(0xffffffffu, ss, o);
    }
    __shared__ float rs[8], rss[8];
    if ((tid & 31) == 0) { rs[tid >> 5] = s; rss[tid >> 5] = ss; }
    __syncthreads();
    float S = 0.f, SSq = 0.f;
#pragma unroll
    for (int w = 0; w < 8; w++) { S += rs[w]; SSq += rss[w]; }
    float mu = S * (1.f / 512.f);
    float var = SSq * (1.f / 512.f) - mu * mu;
    float inv = rsqrtf(var + 1e-5f);
    p[tid] = (x0 - mu) * inv * g[tid] + bta[tid];
    p[tid + 256] = (x1 - mu) * inv * g[tid + 256] + bta[tid + 256];
}

// ----------------------------------------------------------------------------
extern "C" void kernel_launch(void* const* d_in, const int* in_sizes, int n_in,
                              void* d_out, int out_size) {
    const float* input_Q = (const float*)d_in[0];
    const float* input_K = (const float*)d_in[1];
    const float* input_V = (const float*)d_in[2];
    const int* attn_if = (const int*)d_in[4];
    const int* itype = (const int*)d_in[5];
    const float* im = (const float*)d_in[6];
    const float* w_q = (const float*)d_in[9];
    const float* w_k = (const float*)d_in[10];
    const float* w_v = (const float*)d_in[11];
    const float* w_fc = (const float*)d_in[12];
    const float* ln_g = (const float*)d_in[13];
    const float* ln_b = (const float*)d_in[14];
    const float* type_emb = (const float*)d_in[15];
    const float* w_feat = (const float*)d_in[16];

    float* out = (float*)d_out;
    float* attn = out + (size_t)ROWS * DD;

    float *Qp, *Kp, *partial;
    __nv_bfloat16 *Vpb, *ctxb, *wfcb;
    cudaGetSymbolAddress((void**)&Qp, g_Qp);
    cudaGetSymbolAddress((void**)&Kp, g_Kp);
    cudaGetSymbolAddress((void**)&Vpb, g_Vpb);
    cudaGetSymbolAddress((void**)&ctxb, g_ctxb);
    cudaGetSymbolAddress((void**)&wfcb, g_wfcb);
    cudaGetSymbolAddress((void**)&partial, g_partial);

    cvt_wfc<<<DD * DD / 512, 256>>>(w_fc, wfcb);

    // Fused projections (tf32 MMA): Q,K fp32 out; V bf16 out
    dim3 gproj(DD / 128, ROWS / 128, 3);
    proj3_kernel<<<gproj, 256>>>(input_Q, input_K, input_V, w_q, w_k, w_v, Qp, Kp, Vpb);

    // Scores + bias + exp -> attn region (unnormalized e) + row partial sums
    size_t smem = (size_t)(2 * 64 * 68) * sizeof(uint32_t) + (size_t)8 * 64 * 64 * sizeof(__nv_bfloat16);
    cudaFuncSetAttribute(scores_kernel, cudaFuncAttributeMaxDynamicSharedMemorySize, (int)smem);
    dim3 gsc(SS / 64, SS / 64, BB);
    scores_kernel<<<gsc, 256, smem>>>(Qp, Kp, attn_if, itype, im, type_emb, w_feat, attn, partial);

    // av: normalize (in place) + attn @ V -> ctx (bf16 MMA, double-buffered)
    dim3 gav(SS / 64, BB * HH);
    av_mma<<<gav, 256>>>(attn, Vpb, partial, ctxb);

    // FC + residual -> out (bf16 MMA)
    dim3 gfc(DD / 64, ROWS / 128);
    fc_mma<<<gfc, 256>>>(ctxb, wfcb, input_Q, out);

    // LayerNorm in place
    ln_kernel<<<ROWS, 256>>>(out, ln_g, ln_b);
}

// round 12
// speedup vs baseline: 2.7557x; 1.2171x over previous
#include <cuda_runtime.h>
#include <cuda_bf16.h>
#include <math.h>
#include <stdint.h>

// Problem constants
#define BB 4
#define SS 1024
#define DD 512
#define HH 8
#define ROWS (BB*SS)          // 4096
#define NEGV (-1e9f)

// Scratch (device globals; no allocation allowed)
__device__ float g_Qp[ROWS*DD];
__device__ float g_Kp[ROWS*DD];
__device__ __nv_bfloat16 g_Vpb[ROWS*DD];
__device__ __nv_bfloat16 g_ctxb[ROWS*DD];
__device__ __nv_bfloat16 g_wfcb[DD*DD];
__device__ __nv_bfloat16 g_biasb[(size_t)BB*HH*SS*SS];  // precomputed bias [B,H,S,S]
__device__ float g_partial[BB*HH*SS*8];    // per-row, per-ktile(128) exp sums

// ============================ MMA helpers ===================================
__device__ __forceinline__ uint32_t smem_u32(const void* p) {
    return (uint32_t)__cvta_generic_to_shared(p);
}
__device__ __forceinline__ uint32_t f2tf32(float f) {
    uint32_t r; asm("cvt.rna.tf32.f32 %0, %1;" : "=r"(r) : "f"(f)); return r;
}
__device__ __forceinline__ void mma_tf32(float& c0, float& c1, float& c2, float& c3,
        uint32_t a0, uint32_t a1, uint32_t a2, uint32_t a3, uint32_t b0, uint32_t b1) {
    asm volatile("mma.sync.aligned.m16n8k8.row.col.f32.tf32.tf32.f32 "
        "{%0,%1,%2,%3}, {%4,%5,%6,%7}, {%8,%9}, {%0,%1,%2,%3};\n"
        : "+f"(c0), "+f"(c1), "+f"(c2), "+f"(c3)
        : "r"(a0), "r"(a1), "r"(a2), "r"(a3), "r"(b0), "r"(b1));
}
__device__ __forceinline__ void ldsm_x4(uint32_t& r0, uint32_t& r1, uint32_t& r2, uint32_t& r3, uint32_t addr) {
    asm volatile("ldmatrix.sync.aligned.m8n8.x4.shared.b16 {%0,%1,%2,%3}, [%4];\n"
        : "=r"(r0), "=r"(r1), "=r"(r2), "=r"(r3) : "r"(addr));
}
__device__ __forceinline__ void ldsm_x4_t(uint32_t& r0, uint32_t& r1, uint32_t& r2, uint32_t& r3, uint32_t addr) {
    asm volatile("ldmatrix.sync.aligned.m8n8.x4.trans.shared.b16 {%0,%1,%2,%3}, [%4];\n"
        : "=r"(r0), "=r"(r1), "=r"(r2), "=r"(r3) : "r"(addr));
}
__device__ __forceinline__ void mma_bf16(float& c0, float& c1, float& c2, float& c3,
        uint32_t a0, uint32_t a1, uint32_t a2, uint32_t a3, uint32_t b0, uint32_t b1) {
    asm volatile("mma.sync.aligned.m16n8k16.row.col.f32.bf16.bf16.f32 "
        "{%0,%1,%2,%3}, {%4,%5,%6,%7}, {%8,%9}, {%0,%1,%2,%3};\n"
        : "+f"(c0), "+f"(c1), "+f"(c2), "+f"(c3)
        : "r"(a0), "r"(a1), "r"(a2), "r"(a3), "r"(b0), "r"(b1));
}
__device__ __forceinline__ uint32_t bf2x(float a, float b) {
    __nv_bfloat162 h = __float22bfloat162_rn(make_float2(a, b));
    uint32_t u; memcpy(&u, &h, 4); return u;
}

// ----------------------------------------------------------------------------
// tf32 GEMM: C[128,128] = A[.,K]f32 @ B[K,.]f32, BK=16, 256 thr / 8 warps.
// ----------------------------------------------------------------------------
template<bool OUT_BF16>
__device__ __forceinline__ void tf32_gemm_128x128(
        const float* __restrict__ A, const float* __restrict__ B,
        float* __restrict__ Cf, __nv_bfloat16* __restrict__ Cb,
        int K, int lda, int ldb, int ldc, int bm, int bn) {
    __shared__ uint32_t As[128 * 20];
    __shared__ uint32_t Bs[16 * 132];
    const int tid = threadIdx.x;
    const int lane = tid & 31, w = tid >> 5;
    const int wm = w >> 1, wn = w & 1;
    const int g = lane >> 2, t = lane & 3;

    float acc[2][8][4];
#pragma unroll
    for (int mi = 0; mi < 2; mi++)
#pragma unroll
        for (int ni = 0; ni < 8; ni++)
#pragma unroll
            for (int r = 0; r < 4; r++) acc[mi][ni][r] = 0.f;

    const int rA = tid >> 2, fA = tid & 3;
    const int kB = tid >> 5, cB = tid & 31;

    float4 pa0 = *(const float4*)&A[(long)(bm + rA) * lda + 4 * fA];
    float4 pa1 = *(const float4*)&A[(long)(bm + rA + 64) * lda + 4 * fA];
    float4 pb0 = *(const float4*)&B[(long)kB * ldb + bn + 4 * cB];
    float4 pb1 = *(const float4*)&B[(long)(kB + 8) * ldb + bn + 4 * cB];

    for (int k0 = 0; k0 < K; k0 += 16) {
        __syncthreads();
        {
            uint4 v0 = make_uint4(f2tf32(pa0.x), f2tf32(pa0.y), f2tf32(pa0.z), f2tf32(pa0.w));
            uint4 v1 = make_uint4(f2tf32(pa1.x), f2tf32(pa1.y), f2tf32(pa1.z), f2tf32(pa1.w));
            *(uint4*)&As[rA * 20 + 4 * fA] = v0;
            *(uint4*)&As[(rA + 64) * 20 + 4 * fA] = v1;
            uint4 w0 = make_uint4(f2tf32(pb0.x), f2tf32(pb0.y), f2tf32(pb0.z), f2tf32(pb0.w));
            uint4 w1 = make_uint4(f2tf32(pb1.x), f2tf32(pb1.y), f2tf32(pb1.z), f2tf32(pb1.w));
            *(uint4*)&Bs[kB * 132 + 4 * cB] = w0;
            *(uint4*)&Bs[(kB + 8) * 132 + 4 * cB] = w1;
        }
        __syncthreads();
        if (k0 + 16 < K) {
            pa0 = *(const float4*)&A[(long)(bm + rA) * lda + k0 + 16 + 4 * fA];
            pa1 = *(const float4*)&A[(long)(bm + rA + 64) * lda + k0 + 16 + 4 * fA];
            pb0 = *(const float4*)&B[(long)(k0 + 16 + kB) * ldb + bn + 4 * cB];
            pb1 = *(const float4*)&B[(long)(k0 + 24 + kB) * ldb + bn + 4 * cB];
        }
#pragma unroll
        for (int ks = 0; ks < 16; ks += 8) {
            uint32_t a[2][4];
#pragma unroll
            for (int mi = 0; mi < 2; mi++) {
                int rb = (32 * wm + 16 * mi + g) * 20 + ks + t;
                a[mi][0] = As[rb];
                a[mi][1] = As[rb + 8 * 20];
                a[mi][2] = As[rb + 4];
                a[mi][3] = As[rb + 8 * 20 + 4];
            }
            uint32_t bb[8][2];
#pragma unroll
            for (int ni = 0; ni < 8; ni++) {
                int nb = 64 * wn + 8 * ni + g;
                bb[ni][0] = Bs[(ks + t) * 132 + nb];
                bb[ni][1] = Bs[(ks + t + 4) * 132 + nb];
            }
#pragma unroll
            for (int mi = 0; mi < 2; mi++)
#pragma unroll
                for (int ni = 0; ni < 8; ni++)
                    mma_tf32(acc[mi][ni][0], acc[mi][ni][1], acc[mi][ni][2], acc[mi][ni][3],
                             a[mi][0], a[mi][1], a[mi][2], a[mi][3], bb[ni][0], bb[ni][1]);
        }
    }

#pragma unroll
    for (int mi = 0; mi < 2; mi++)
#pragma unroll
        for (int ni = 0; ni < 8; ni++) {
            long r0 = bm + 32 * wm + 16 * mi + g;
            long cc = bn + 64 * wn + 8 * ni + 2 * t;
            if (OUT_BF16) {
                *(__nv_bfloat162*)&Cb[r0 * ldc + cc] =
                    __float22bfloat162_rn(make_float2(acc[mi][ni][0], acc[mi][ni][1]));
                *(__nv_bfloat162*)&Cb[(r0 + 8) * ldc + cc] =
                    __float22bfloat162_rn(make_float2(acc[mi][ni][2], acc[mi][ni][3]));
            } else {
                *(float2*)&Cf[r0 * ldc + cc] = make_float2(acc[mi][ni][0], acc[mi][ni][1]);
                *(float2*)&Cf[(r0 + 8) * ldc + cc] = make_float2(acc[mi][ni][2], acc[mi][ni][3]);
            }
        }
}

// Fused Q/K/V projections; V writes bf16.
__global__ __launch_bounds__(256) void proj3_kernel(
        const float* __restrict__ Aq, const float* __restrict__ Ak, const float* __restrict__ Av,
        const float* __restrict__ Wq, const float* __restrict__ Wk, const float* __restrict__ Wv,
        float* __restrict__ Cq, float* __restrict__ Ck, __nv_bfloat16* __restrict__ Cvb) {
    const int z = blockIdx.z;
    const float* A = (z == 0) ? Aq : (z == 1) ? Ak : Av;
    const float* B = (z == 0) ? Wq : (z == 1) ? Wk : Wv;
    if (z == 2)
        tf32_gemm_128x128<true>(A, B, nullptr, Cvb, DD, DD, DD, DD, blockIdx.y * 128, blockIdx.x * 128);
    else
        tf32_gemm_128x128<false>(A, B, (z == 0) ? Cq : Ck, nullptr, DD, DD, DD, DD, blockIdx.y * 128, blockIdx.x * 128);
}

// ----------------------------------------------------------------------------
// Bias precompute: per pair (b,q,k) compute all 8 head biases -> bf16 [B,H,S,S].
// grid 16384 x 256 threads, 1 pair/thread.
// ----------------------------------------------------------------------------
__global__ __launch_bounds__(256) void bias_kernel(
        const int* __restrict__ attn_if, const int* __restrict__ itype,
        const float* __restrict__ im, const float* __restrict__ type_emb,
        const float* __restrict__ w_feat, __nv_bfloat16* __restrict__ biasg) {
    __shared__ float wf[6][8];
    const int tid = threadIdx.x;
    if (tid < 48) wf[tid / 8][tid % 8] = w_feat[tid];
    __syncthreads();

    const long pair = (long)blockIdx.x * 256 + tid;      // 0 .. 4M-1
    const int b = (int)(pair >> 20);
    const int q = (int)((pair >> 10) & 1023);
    const int k = (int)(pair & 1023);

    float bias[8];
    if (attn_if[pair] != 0) {
#pragma unroll
        for (int h = 0; h < 8; h++) bias[h] = NEGV;
    } else {
        int tt = itype[pair];
        const float* e = type_emb + (long)tt * 8;
        const float2* imp = (const float2*)(im + pair * 6);
        float2 p0 = imp[0], p1 = imp[1], p2 = imp[2];
#pragma unroll
        for (int h = 0; h < 8; h++) {
            float s = p0.x * wf[0][h] + p0.y * wf[1][h] + p1.x * wf[2][h]
                    + p1.y * wf[3][h] + p2.x * wf[4][h] + p2.y * wf[5][h];
            bias[h] = fmaxf(s, 0.f) + e[h];
        }
    }
#pragma unroll
    for (int h = 0; h < 8; h++)
        biasg[(((long)(b * HH + h) * SS + q) << 10) + k] = __float2bfloat16(bias[h]);
}

// ----------------------------------------------------------------------------
// Scores: one 128x128x64 tf32 MMA per block. Block = (k-tile 128, q-tile 128,
// b*8+h). Reads precomputed bias tile from gmem, applies exp, writes raw e
// to attn region + per-row per-ktile(128) partial sums.
// 256 threads / 8 warps, warp grid 4x2, warp tile 32x64.
// ----------------------------------------------------------------------------
__global__ __launch_bounds__(256) void scores_kernel(
        const float* __restrict__ Qp, const float* __restrict__ Kp,
        const __nv_bfloat16* __restrict__ biasg,
        float* __restrict__ attn_out, float* __restrict__ partial) {
    extern __shared__ char smraw[];
    uint32_t* Qt = (uint32_t*)smraw;          // [128 q][68] tf32
    uint32_t* Kt = Qt + 128 * 68;             // [128 k][68] tf32
    __shared__ float smsum[128][2];

    const int bz = blockIdx.z;                // b*8 + h
    const int b = bz >> 3, h = bz & 7;
    const int q0 = blockIdx.y * 128;
    const int k0 = blockIdx.x * 128;
    const int tid = threadIdx.x;
    const int lane = tid & 31, w = tid >> 5;
    const int wm = w >> 1, wn = w & 1;        // 4x2 warp grid
    const int g = lane >> 2, t = lane & 3;

    // Stage Q/K tiles (tf32 rounding): 8 passes x 16 rows
    const int fL = tid & 15, rL = tid >> 4;
#pragma unroll
    for (int l = 0; l < 8; l++) {
        int r = rL + l * 16;
        float4 q = *(const float4*)&Qp[((long)(b * SS + q0 + r)) * DD + h * 64 + 4 * fL];
        float4 k = *(const float4*)&Kp[((long)(b * SS + k0 + r)) * DD + h * 64 + 4 * fL];
        *(uint4*)&Qt[r * 68 + 4 * fL] = make_uint4(f2tf32(q.x), f2tf32(q.y), f2tf32(q.z), f2tf32(q.w));
        *(uint4*)&Kt[r * 68 + 4 * fL] = make_uint4(f2tf32(k.x), f2tf32(k.y), f2tf32(k.z), f2tf32(k.w));
    }
    __syncthreads();

    float acc[2][8][4];
#pragma unroll
    for (int mi = 0; mi < 2; mi++)
#pragma unroll
        for (int ni = 0; ni < 8; ni++)
#pragma unroll
            for (int r = 0; r < 4; r++) acc[mi][ni][r] = 0.f;

#pragma unroll
    for (int k8 = 0; k8 < 64; k8 += 8) {
        uint32_t a[2][4];
#pragma unroll
        for (int mi = 0; mi < 2; mi++) {
            int rb = (32 * wm + 16 * mi + g) * 68 + k8 + t;
            a[mi][0] = Qt[rb];
            a[mi][1] = Qt[rb + 8 * 68];
            a[mi][2] = Qt[rb + 4];
            a[mi][3] = Qt[rb + 8 * 68 + 4];
        }
        uint32_t bb[8][2];
#pragma unroll
        for (int ni = 0; ni < 8; ni++) {
            int nb = (64 * wn + 8 * ni + g) * 68 + k8 + t;
            bb[ni][0] = Kt[nb];
            bb[ni][1] = Kt[nb + 4];
        }
#pragma unroll
        for (int mi = 0; mi < 2; mi++)
#pragma unroll
            for (int ni = 0; ni < 8; ni++)
                mma_tf32(acc[mi][ni][0], acc[mi][ni][1], acc[mi][ni][2], acc[mi][ni][3],
                         a[mi][0], a[mi][1], a[mi][2], a[mi][3], bb[ni][0], bb[ni][1]);
    }

    // Epilogue: e = exp(score*0.125 + bias), write raw e + row partials
    const __nv_bfloat16* bp = biasg + ((long)bz * SS + q0) * SS + k0;
    float* outp = attn_out + ((long)bz * SS + q0) * SS + k0;
    float rsum[2][2] = {{0.f, 0.f}, {0.f, 0.f}};     // [mi][row-half]
#pragma unroll
    for (int mi = 0; mi < 2; mi++) {
        const int row0 = 32 * wm + 16 * mi + g;
#pragma unroll
        for (int ni = 0; ni < 8; ni++) {
            int col = 64 * wn + 8 * ni + 2 * t;
            __nv_bfloat162 bA = *(const __nv_bfloat162*)&bp[(long)row0 * SS + col];
            __nv_bfloat162 bB = *(const __nv_bfloat162*)&bp[(long)(row0 + 8) * SS + col];
            float e0 = __expf(acc[mi][ni][0] * 0.125f + __bfloat162float(bA.x));
            float e1 = __expf(acc[mi][ni][1] * 0.125f + __bfloat162float(bA.y));
            float e2 = __expf(acc[mi][ni][2] * 0.125f + __bfloat162float(bB.x));
            float e3 = __expf(acc[mi][ni][3] * 0.125f + __bfloat162float(bB.y));
            *(float2*)&outp[(long)row0 * SS + col] = make_float2(e0, e1);
            *(float2*)&outp[(long)(row0 + 8) * SS + col] = make_float2(e2, e3);
            rsum[mi][0] += e0 + e1;
            rsum[mi][1] += e2 + e3;
        }
    }
    // Reduce over t (4 lanes share a row), then across the 2 wn warps via smem
#pragma unroll
    for (int mi = 0; mi < 2; mi++) {
#pragma unroll
        for (int hf = 0; hf < 2; hf++) {
            float s = rsum[mi][hf];
            s += __shfl_xor_sync(0xffffffffu, s, 1);
            s += __shfl_xor_sync(0xffffffffu, s, 2);
            if (t == 0) smsum[32 * wm + 16 * mi + 8 * hf + g][wn] = s;
        }
    }
    __syncthreads();
    if (tid < 128)
        partial[((long)bz * SS + q0 + tid) * 8 + blockIdx.x] = smsum[tid][0] + smsum[tid][1];
}

// ----------------------------------------------------------------------------
// av: ctx = softmax(attn) @ V. 64-row q-tiles, double-buffered smem.
// Normalizes raw e by row sums, writes normalized attn f32 IN PLACE,
// bf16 MMA with V. grid (S/64, B*H), 256 threads / 8 warps.
// ----------------------------------------------------------------------------
__global__ __launch_bounds__(256) void av_mma(float* attn,
                                              const __nv_bfloat16* __restrict__ Vb,
                                              const float* __restrict__ partial,
                                              __nv_bfloat16* __restrict__ ctxb) {
    __shared__ __nv_bfloat16 As[2][64 * 40];
    __shared__ __nv_bfloat16 Bs[2][32 * 72];
    __shared__ float invs[64];
    const int z = blockIdx.y, b = z >> 3, h = z & 7;
    const int q0 = blockIdx.x * 64;
    float* A = attn + (long)z * SS * SS + (long)q0 * SS;
    const __nv_bfloat16* Bv = Vb + (long)b * SS * DD + h * 64;
    const int tid = threadIdx.x;
    const int lane = tid & 31, w = tid >> 5;
    const int wm = w >> 1, wn = w & 1;

    // Deterministic row sums: fixed-order sum of 8 partials per row.
    if (tid < 64) {
        const float* pp = partial + ((long)z * SS + q0 + tid) * 8;
        float s = 0.f;
#pragma unroll
        for (int i = 0; i < 8; i++) s += pp[i];
        invs[tid] = 1.f / s;
    }
    __syncthreads();

    float c[4][4];
#pragma unroll
    for (int ni = 0; ni < 4; ni++)
#pragma unroll
        for (int r = 0; r < 4; r++) c[ni][r] = 0.f;

    const int arow = tid >> 2, aq = tid & 3;
    const int brow = tid >> 3, bseg = tid & 7;
    const float ia = invs[arow];

    {
        float4 p0 = *(const float4*)&A[(long)arow * SS + 8 * aq];
        float4 p1 = *(const float4*)&A[(long)arow * SS + 8 * aq + 4];
        uint4 pb = *(const uint4*)&Bv[(long)brow * DD + 8 * bseg];
        float4 u0 = make_float4(p0.x * ia, p0.y * ia, p0.z * ia, p0.w * ia);
        float4 u1 = make_float4(p1.x * ia, p1.y * ia, p1.z * ia, p1.w * ia);
        *(float4*)&A[(long)arow * SS + 8 * aq] = u0;
        *(float4*)&A[(long)arow * SS + 8 * aq + 4] = u1;
        *(uint4*)&As[0][arow * 40 + 8 * aq] =
            make_uint4(bf2x(u0.x, u0.y), bf2x(u0.z, u0.w), bf2x(u1.x, u1.y), bf2x(u1.z, u1.w));
        *(uint4*)&Bs[0][brow * 72 + 8 * bseg] = pb;
    }
    __syncthreads();

    for (int k0 = 0; k0 < SS; k0 += 32) {
        const int cur = (k0 >> 5) & 1;
        const bool more = (k0 + 32 < SS);
        float4 p0, p1; uint4 pb;
        if (more) {
            p0 = *(const float4*)&A[(long)arow * SS + k0 + 32 + 8 * aq];
            p1 = *(const float4*)&A[(long)arow * SS + k0 + 32 + 8 * aq + 4];
            pb = *(const uint4*)&Bv[(long)(k0 + 32 + brow) * DD + 8 * bseg];
        }
#pragma unroll
        for (int kk = 0; kk < 32; kk += 16) {
            uint32_t a[4];
            {
                uint32_t addr = smem_u32(&As[cur][(16 * wm + (lane & 15)) * 40 + kk + ((lane >> 4) << 3)]);
                ldsm_x4(a[0], a[1], a[2], a[3], addr);
            }
            uint32_t bf[2][4];
#pragma unroll
            for (int nb = 0; nb < 2; nb++) {
                uint32_t addr = smem_u32(&Bs[cur][(kk + (lane & 15)) * 72 + 32 * wn + 16 * nb + ((lane >> 4) << 3)]);
                ldsm_x4_t(bf[nb][0], bf[nb][1], bf[nb][2], bf[nb][3], addr);
            }
#pragma unroll
            for (int ni = 0; ni < 4; ni++) {
                int nb = ni >> 1, h2 = (ni & 1) * 2;
                mma_bf16(c[ni][0], c[ni][1], c[ni][2], c[ni][3],
                         a[0], a[1], a[2], a[3], bf[nb][h2], bf[nb][h2 + 1]);
            }
        }
        if (more) {
            float4 u0 = make_float4(p0.x * ia, p0.y * ia, p0.z * ia, p0.w * ia);
            float4 u1 = make_float4(p1.x * ia, p1.y * ia, p1.z * ia, p1.w * ia);
            *(float4*)&A[(long)arow * SS + k0 + 32 + 8 * aq] = u0;
            *(float4*)&A[(long)arow * SS + k0 + 32 + 8 * aq + 4] = u1;
            *(uint4*)&As[1 - cur][arow * 40 + 8 * aq] =
                make_uint4(bf2x(u0.x, u0.y), bf2x(u0.z, u0.w), bf2x(u1.x, u1.y), bf2x(u1.z, u1.w));
            *(uint4*)&Bs[1 - cur][brow * 72 + 8 * bseg] = pb;
        }
        __syncthreads();
    }

    __nv_bfloat16* C = ctxb + (long)b * SS * DD + (long)q0 * DD + h * 64;
#pragma unroll
    for (int ni = 0; ni < 4; ni++) {
        int r = 16 * wm + (lane >> 2);
        int cc = 32 * wn + 8 * ni + (lane & 3) * 2;
        *(__nv_bfloat162*)&C[(long)r * DD + cc] =
            __float22bfloat162_rn(make_float2(c[ni][0], c[ni][1]));
        *(__nv_bfloat162*)&C[(long)(r + 8) * DD + cc] =
            __float22bfloat162_rn(make_float2(c[ni][2], c[ni][3]));
    }
}

// ----------------------------------------------------------------------------
// bf16 GEMM (FC): C[128,64] = A[128,K] @ B[K,64] + Res, f32 out.
// ----------------------------------------------------------------------------
__global__ __launch_bounds__(256) void fc_mma(const __nv_bfloat16* __restrict__ A,
                                              const __nv_bfloat16* __restrict__ wfcb,
                                              const float* __restrict__ res,
                                              float* __restrict__ out) {
    __shared__ __nv_bfloat16 As[128 * 40];
    __shared__ __nv_bfloat16 Bs[32 * 72];
    const int bn = blockIdx.x * 64;
    const long bm = (long)blockIdx.y * 128;
    const __nv_bfloat16* Ab = A + bm * DD;
    const __nv_bfloat16* B = wfcb + bn;
    const float* Res = res + bm * DD + bn;
    float* Cf = out + bm * DD + bn;
    const int tid = threadIdx.x;
    const int lane = tid & 31, w = tid >> 5;
    const int wm = w >> 1, wn = w & 1;

    float c[2][4][4];
#pragma unroll
    for (int mi = 0; mi < 2; mi++)
#pragma unroll
        for (int ni = 0; ni < 4; ni++)
#pragma unroll
            for (int r = 0; r < 4; r++) c[mi][ni][r] = 0.f;

    const int arow = tid >> 2, aq = tid & 3;
    const int brow = tid >> 3, bseg = tid & 7;

    uint4 pa0 = *(const uint4*)&Ab[(long)arow * DD + 8 * aq];
    uint4 pa1 = *(const uint4*)&Ab[(long)(arow + 64) * DD + 8 * aq];
    uint4 pb  = *(const uint4*)&B[(long)brow * DD + 8 * bseg];

    for (int k0 = 0; k0 < DD; k0 += 32) {
        __syncthreads();
        *(uint4*)&As[arow * 40 + 8 * aq] = pa0;
        *(uint4*)&As[(arow + 64) * 40 + 8 * aq] = pa1;
        *(uint4*)&Bs[brow * 72 + 8 * bseg] = pb;
        __syncthreads();
        if (k0 + 32 < DD) {
            pa0 = *(const uint4*)&Ab[(long)arow * DD + k0 + 32 + 8 * aq];
            pa1 = *(const uint4*)&Ab[(long)(arow + 64) * DD + k0 + 32 + 8 * aq];
            pb  = *(const uint4*)&B[(long)(k0 + 32 + brow) * DD + 8 * bseg];
        }
#pragma unroll
        for (int kk = 0; kk < 32; kk += 16) {
            uint32_t a[2][4];
#pragma unroll
            for (int mi = 0; mi < 2; mi++) {
                uint32_t addr = smem_u32(&As[(32 * wm + 16 * mi + (lane & 15)) * 40 + kk + ((lane >> 4) << 3)]);
                ldsm_x4(a[mi][0], a[mi][1], a[mi][2], a[mi][3], addr);
            }
            uint32_t bf[2][4];
#pragma unroll
            for (int nb = 0; nb < 2; nb++) {
                uint32_t addr = smem_u32(&Bs[(kk + (lane & 15)) * 72 + 32 * wn + 16 * nb + ((lane >> 4) << 3)]);
                ldsm_x4_t(bf[nb][0], bf[nb][1], bf[nb][2], bf[nb][3], addr);
            }
#pragma unroll
            for (int mi = 0; mi < 2; mi++)
#pragma unroll
                for (int ni = 0; ni < 4; ni++) {
                    int nb = ni >> 1, h2 = (ni & 1) * 2;
                    mma_bf16(c[mi][ni][0], c[mi][ni][1], c[mi][ni][2], c[mi][ni][3],
                             a[mi][0], a[mi][1], a[mi][2], a[mi][3], bf[nb][h2], bf[nb][h2 + 1]);
                }
        }
    }

#pragma unroll
    for (int mi = 0; mi < 2; mi++)
#pragma unroll
        for (int ni = 0; ni < 4; ni++) {
            int r = 32 * wm + 16 * mi + (lane >> 2);
            int cc = 32 * wn + 8 * ni + (lane & 3) * 2;
            float2 r0 = *(const float2*)&Res[(long)r * DD + cc];
            float2 r1 = *(const float2*)&Res[(long)(r + 8) * DD + cc];
            *(float2*)&Cf[(long)r * DD + cc] = make_float2(c[mi][ni][0] + r0.x, c[mi][ni][1] + r0.y);
            *(float2*)&Cf[(long)(r + 8) * DD + cc] = make_float2(c[mi][ni][2] + r1.x, c[mi][ni][3] + r1.y);
        }
}

__global__ void cvt_wfc(const float* __restrict__ w, __nv_bfloat16* __restrict__ o) {
    int i = blockIdx.x * 256 + threadIdx.x;
    float2 v = *(const float2*)&w[2 * i];
    *(__nv_bfloat162*)&o[2 * i] = __float22bfloat162_rn(v);
}

// ----------------------------------------------------------------------------
// In-place LayerNorm over last dim (512). grid = ROWS, 256 threads.
// ----------------------------------------------------------------------------
__global__ void ln_kernel(float* __restrict__ out, const float* __restrict__ g,
                          const float* __restrict__ bta) {
    const long row = blockIdx.x;
    float* p = out + row * DD;
    const int tid = threadIdx.x;
    float x0 = p[tid], x1 = p[tid + 256];
    float s = x0 + x1, ss = x0 * x0 + x1 * x1;
#pragma unroll
    for (int o = 16; o; o >>= 1) {
        s += __shfl_xor_sync(0xffffffffu, s, o);
        ss += __shfl_xor_sync(0xffffffffu, ss, o);
    }
    __shared__ float rs[8], rss[8];
    if ((tid & 31) == 0) { rs[tid >> 5] = s; rss[tid >> 5] = ss; }
    __syncthreads();
    float S = 0.f, SSq = 0.f;
#pragma unroll
    for (int w = 0; w < 8; w++) { S += rs[w]; SSq += rss[w]; }
    float mu = S * (1.f / 512.f);
    float var = SSq * (1.f / 512.f) - mu * mu;
    float inv = rsqrtf(var + 1e-5f);
    p[tid] = (x0 - mu) * inv * g[tid] + bta[tid];
    p[tid + 256] = (x1 - mu) * inv * g[tid + 256] + bta[tid + 256];
}

// ----------------------------------------------------------------------------
extern "C" void kernel_launch(void* const* d_in, const int* in_sizes, int n_in,
                              void* d_out, int out_size) {
    const float* input_Q = (const float*)d_in[0];
    const float* input_K = (const float*)d_in[1];
    const float* input_V = (const float*)d_in[2];
    const int* attn_if = (const int*)d_in[4];
    const int* itype = (const int*)d_in[5];
    const float* im = (const float*)d_in[6];
    const float* w_q = (const float*)d_in[9];
    const float* w_k = (const float*)d_in[10];
    const float* w_v = (const float*)d_in[11];
    const float* w_fc = (const float*)d_in[12];
    const float* ln_g = (const float*)d_in[13];
    const float* ln_b = (const float*)d_in[14];
    const float* type_emb = (const float*)d_in[15];
    const float* w_feat = (const float*)d_in[16];

    float* out = (float*)d_out;
    float* attn = out + (size_t)ROWS * DD;

    float *Qp, *Kp, *partial;
    __nv_bfloat16 *Vpb, *ctxb, *wfcb, *biasb;
    cudaGetSymbolAddress((void**)&Qp, g_Qp);
    cudaGetSymbolAddress((void**)&Kp, g_Kp);
    cudaGetSymbolAddress((void**)&Vpb, g_Vpb);
    cudaGetSymbolAddress((void**)&ctxb, g_ctxb);
    cudaGetSymbolAddress((void**)&wfcb, g_wfcb);
    cudaGetSymbolAddress((void**)&biasb, g_biasb);
    cudaGetSymbolAddress((void**)&partial, g_partial);

    cvt_wfc<<<DD * DD / 512, 256>>>(w_fc, wfcb);

    // Bias precompute -> bf16 [B,H,S,S]
    bias_kernel<<<BB * SS * SS / 256, 256>>>(attn_if, itype, im, type_emb, w_feat, biasb);

    // Fused projections (tf32 MMA): Q,K fp32 out; V bf16 out
    dim3 gproj(DD / 128, ROWS / 128, 3);
    proj3_kernel<<<gproj, 256>>>(input_Q, input_K, input_V, w_q, w_k, w_v, Qp, Kp, Vpb);

    // Scores (tf32 MMA 128x128x64) + bias + exp -> attn (raw e) + partials
    size_t smem = (size_t)(2 * 128 * 68) * sizeof(uint32_t);
    cudaFuncSetAttribute(scores_kernel, cudaFuncAttributeMaxDynamicSharedMemorySize, (int)smem);
    dim3 gsc(SS / 128, SS / 128, BB * HH);
    scores_kernel<<<gsc, 256, smem>>>(Qp, Kp, biasb, attn, partial);

    // av: normalize (in place) + attn @ V -> ctx (bf16 MMA, double-buffered)
    dim3 gav(SS / 64, BB * HH);
    av_mma<<<gav, 256>>>(attn, Vpb, partial, ctxb);

    // FC + residual -> out (bf16 MMA)
    dim3 gfc(DD / 64, ROWS / 128);
    fc_mma<<<gfc, 256>>>(ctxb, wfcb, input_Q, out);

    // LayerNorm in place
    ln_kernel<<<ROWS, 256>>>(out, ln_g, ln_b);
}